// round 6
// baseline (speedup 1.0000x reference)
#include <cuda_runtime.h>
#include <cuda_fp16.h>
#include <math.h>
#include <stdint.h>

// Problem constants
#define BATCH 8
#define CDIM  512
#define LDIM  4096
#define HEADS 8
#define DIMH  64
#define HID   512   // HEADS*DIMH

// ---------------------------------------------------------------------------
// Scratch (static __device__ arrays)
// ---------------------------------------------------------------------------
__device__ float  g_k  [(size_t)BATCH * HID * LDIM];      // fp32 k logits [b][512][4096]
__device__ __half g_kh [(size_t)BATCH * HID * LDIM];      // fp16 softmaxed k
__device__ __half g_v  [(size_t)BATCH * HID * LDIM];      // fp16 v
__device__ float  g_part[(size_t)4 * 64 * DIMH * DIMH];   // context split-K partials
__device__ float  g_ctx [(size_t)64 * DIMH * DIMH];       // context [bh][d*64+e]

__device__ __half g_xT  [(size_t)BATCH * LDIM * CDIM];    // fp16(x)^T [b][l][c]
__device__ __half g_wk_h[(size_t)(2 * HID) * CDIM];       // fp16(64*W_kv) hi
__device__ __half g_wk_l[(size_t)(2 * HID) * CDIM];       // lo
__device__ __half g_wo_h[(size_t)CDIM * HID];             // fp16(64*W_out) hi
__device__ __half g_wo_l[(size_t)CDIM * HID];
__device__ __half g_Abt [(size_t)BATCH * CDIM * HID];     // fp16(A_b^T) [b][c][hid]
__device__ __half g_Mb_h[(size_t)BATCH * CDIM * CDIM];    // fp16(2048*M_b) hi
__device__ __half g_Mb_l[(size_t)BATCH * CDIM * CDIM];    // lo

// ---------------------------------------------------------------------------
// PTX helpers
// ---------------------------------------------------------------------------
__device__ __forceinline__ uint32_t smem_u32(const void* p) {
    uint32_t a;
    asm("{ .reg .u64 t; cvta.to.shared.u64 t, %1; cvt.u32.u64 %0, t; }" : "=r"(a) : "l"(p));
    return a;
}
__device__ __forceinline__ void cp_async16(uint32_t dst, const void* src) {
    asm volatile("cp.async.cg.shared.global [%0], [%1], 16;" :: "r"(dst), "l"(src));
}
__device__ __forceinline__ void cp_commit() { asm volatile("cp.async.commit_group;" ::: "memory"); }
__device__ __forceinline__ void cp_wait1()  { asm volatile("cp.async.wait_group 1;" ::: "memory"); }
__device__ __forceinline__ void cp_wait0()  { asm volatile("cp.async.wait_group 0;" ::: "memory"); }
__device__ __forceinline__ void ldsm_x4(uint32_t* r, uint32_t addr) {
    asm volatile("ldmatrix.sync.aligned.m8n8.x4.shared.b16 {%0,%1,%2,%3}, [%4];"
                 : "=r"(r[0]), "=r"(r[1]), "=r"(r[2]), "=r"(r[3]) : "r"(addr));
}
__device__ __forceinline__ void mma_fp16(float* c, const uint32_t* a, const uint32_t* b) {
    asm volatile(
        "mma.sync.aligned.m16n8k16.row.col.f32.f16.f16.f32 "
        "{%0,%1,%2,%3}, {%4,%5,%6,%7}, {%8,%9}, {%0,%1,%2,%3};"
        : "+f"(c[0]), "+f"(c[1]), "+f"(c[2]), "+f"(c[3])
        : "r"(a[0]), "r"(a[1]), "r"(a[2]), "r"(a[3]), "r"(b[0]), "r"(b[1]));
}

// ---------------------------------------------------------------------------
// tc2: C[b][m][n] = sum_k (Ah+Al)[m,k] * Bh[n,k]   (fp16 2-term, K=512)
// CTA tile 128x256, K-chunk 64, 3-stage cp.async pipeline.
// 512 threads = 16 warps (4Mx4N), warp tile 32x64.
// Hi-pass then lo-pass MMA issue (breaks accumulator RAW chains).
// MODE 0: fp32 out = acc*invScale (+bias)
// MODE 1: fp16 hi/lo split of acc*hScale
// MODE 2: GEMM1 — m0<512 writes fp32 k; m0>=512 writes fp16 v at row-512.
// ---------------------------------------------------------------------------
#define ROWB   144
#define A_MAT  (128 * ROWB)          // 18432
#define B_MAT  (256 * ROWB)          // 36864
#define STAGE  (2 * A_MAT + B_MAT)   // 73728
#define TC_SMEM (3 * STAGE)          // 221184

template<int MODE>
__global__ __launch_bounds__(512, 1)
void tc2(const __half* __restrict__ Ah, const __half* __restrict__ Al, long aBatch,
         const __half* __restrict__ Bh, long bBatch,
         float* __restrict__ Cf, __half* __restrict__ Ch, __half* __restrict__ Cl,
         long cBatch, int cRow,
         const float* __restrict__ bias, float invScale, float hScale)
{
    extern __shared__ char smem[];
    const uint32_t sb = smem_u32(smem);
    const int t = threadIdx.x;
    const int lane = t & 31;
    const int warp = t >> 5;           // 0..15
    const int wm = (warp & 3) * 32;    // warp M offset (4 tiles of 32)
    const int wn = (warp >> 2) * 64;   // warp N offset (4 tiles of 64)
    const int n0 = blockIdx.x * 256;
    const int m0 = blockIdx.y * 128;
    const int b = blockIdx.z;

    Ah += (size_t)b * aBatch;  Al += (size_t)b * aBatch;
    Bh += (size_t)b * bBatch;

    const uint32_t aOff = (uint32_t)((lane & 15) * ROWB + (lane >> 4) * 16);
    const uint32_t bOff = (uint32_t)(((lane & 7) + ((lane >> 4) << 3)) * ROWB
                                     + (((lane >> 3) & 1) * 16));

    float acc[2][8][4] = {};   // [mt][nt][reg]

    auto load_chunk = [&](int c, int buf) {
        const int k0 = c * 64;
        const uint32_t base = sb + (uint32_t)buf * STAGE;
        #pragma unroll
        for (int i = 0; i < 2; i++) {           // A hi+lo (1024 segs each)
            const int idx = t + i * 512;        // 0..1023
            const int r = idx >> 3, s = idx & 7;
            const uint32_t dst = base + (uint32_t)(r * ROWB + s * 16);
            const size_t ga = (size_t)(m0 + r) * 512 + k0 + s * 8;
            cp_async16(dst,         Ah + ga);
            cp_async16(dst + A_MAT, Al + ga);
        }
        #pragma unroll
        for (int i = 0; i < 4; i++) {           // B (2048 segs)
            const int idx = t + i * 512;        // 0..2047
            const int r = idx >> 3, s = idx & 7;
            const uint32_t dst = base + 2 * A_MAT + (uint32_t)(r * ROWB + s * 16);
            cp_async16(dst, Bh + (size_t)(n0 + r) * 512 + k0 + s * 8);
        }
    };

    load_chunk(0, 0); cp_commit();
    load_chunk(1, 1); cp_commit();

    for (int c = 0; c < 8; c++) {
        if (c < 7) cp_wait1(); else cp_wait0();
        __syncthreads();
        if (c < 6) { load_chunk(c + 2, (c + 2) % 3); cp_commit(); }

        const uint32_t base = sb + (uint32_t)(c % 3) * STAGE;
        #pragma unroll
        for (int ks = 0; ks < 4; ks++) {
            const uint32_t kb = (uint32_t)(ks * 32);
            uint32_t ah[2][4], al[2][4];
            #pragma unroll
            for (int mt = 0; mt < 2; mt++) {
                const uint32_t ra = base + (uint32_t)((wm + mt * 16) * ROWB) + aOff + kb;
                ldsm_x4(ah[mt], ra);
                ldsm_x4(al[mt], ra + A_MAT);
            }
            uint32_t bfr[8][2];
            #pragma unroll
            for (int np = 0; np < 4; np++) {
                uint32_t r4[4];
                const uint32_t rb = base + 2 * A_MAT
                    + (uint32_t)((wn + np * 16) * ROWB) + bOff + kb;
                ldsm_x4(r4, rb);
                bfr[np * 2][0] = r4[0]; bfr[np * 2][1] = r4[1];
                bfr[np * 2 + 1][0] = r4[2]; bfr[np * 2 + 1][1] = r4[3];
            }
            // hi pass, then lo pass: per-accumulator RAW distance = 32 MMAs
            #pragma unroll
            for (int mt = 0; mt < 2; mt++)
                #pragma unroll
                for (int nt = 0; nt < 8; nt++)
                    mma_fp16(acc[mt][nt], ah[mt], bfr[nt]);
            #pragma unroll
            for (int mt = 0; mt < 2; mt++)
                #pragma unroll
                for (int nt = 0; nt < 8; nt++)
                    mma_fp16(acc[mt][nt], al[mt], bfr[nt]);
        }
        __syncthreads();
    }

    // ---- epilogue ----
    #pragma unroll
    for (int mt = 0; mt < 2; mt++) {
        const int row = m0 + wm + mt * 16 + (lane >> 2);
        float bv0 = 0.0f, bv1 = 0.0f;
        if (MODE == 0 && bias) { bv0 = bias[row]; bv1 = bias[row + 8]; }
        #pragma unroll
        for (int nt = 0; nt < 8; nt++) {
            const int col = n0 + wn + nt * 8 + 2 * (lane & 3);
            if (MODE == 0) {
                float* c0 = Cf + (size_t)b * cBatch + (size_t)row * cRow + col;
                float* c1 = Cf + (size_t)b * cBatch + (size_t)(row + 8) * cRow + col;
                *(float2*)c0 = make_float2(acc[mt][nt][0] * invScale + bv0,
                                           acc[mt][nt][1] * invScale + bv0);
                *(float2*)c1 = make_float2(acc[mt][nt][2] * invScale + bv1,
                                           acc[mt][nt][3] * invScale + bv1);
            } else if (MODE == 1) {
                #pragma unroll
                for (int hf = 0; hf < 2; hf++) {
                    const int rr = row + hf * 8;
                    const float v0 = acc[mt][nt][hf * 2 + 0] * hScale;
                    const float v1 = acc[mt][nt][hf * 2 + 1] * hScale;
                    const __half h0 = __float2half_rn(v0);
                    const __half h1 = __float2half_rn(v1);
                    const __half l0 = __float2half_rn(v0 - __half2float(h0));
                    const __half l1 = __float2half_rn(v1 - __half2float(h1));
                    const size_t o = (size_t)b * cBatch + (size_t)rr * cRow + col;
                    *(__half2*)(Ch + o) = __halves2half2(h0, h1);
                    *(__half2*)(Cl + o) = __halves2half2(l0, l1);
                }
            } else {  // MODE 2: k fp32 / v fp16
                if (m0 < 512) {
                    float* c0 = Cf + (size_t)b * cBatch + (size_t)row * cRow + col;
                    float* c1 = Cf + (size_t)b * cBatch + (size_t)(row + 8) * cRow + col;
                    *(float2*)c0 = make_float2(acc[mt][nt][0] * invScale,
                                               acc[mt][nt][1] * invScale);
                    *(float2*)c1 = make_float2(acc[mt][nt][2] * invScale,
                                               acc[mt][nt][3] * invScale);
                } else {
                    #pragma unroll
                    for (int hf = 0; hf < 2; hf++) {
                        const int rr = row - 512 + hf * 8;
                        const float v0 = acc[mt][nt][hf * 2 + 0] * invScale;
                        const float v1 = acc[mt][nt][hf * 2 + 1] * invScale;
                        const size_t o = (size_t)b * cBatch + (size_t)rr * cRow + col;
                        *(__half2*)(Ch + o) =
                            __halves2half2(__float2half_rn(v0), __float2half_rn(v1));
                    }
                }
            }
        }
    }
}

// ---------------------------------------------------------------------------
// context_mma: part[sp][bh][d][e] = sum_{n in split sp} kh[d,n] * v[e,n]
// grid (4 splits, 64 bh), 256 threads, fp16 MMA, double-buffered cp.async.
// ---------------------------------------------------------------------------
#define CTX_ROWB 144
#define CTX_MAT  (64 * CTX_ROWB)        // 9216
#define CTX_STAGE (2 * CTX_MAT)         // 18432

__global__ __launch_bounds__(256)
void context_mma(const __half* __restrict__ kh, const __half* __restrict__ v,
                 float* __restrict__ part)
{
    __shared__ __align__(16) char smem[2 * CTX_STAGE];
    const uint32_t sb = smem_u32(smem);
    const int t = threadIdx.x;
    const int lane = t & 31;
    const int warp = t >> 5;
    const int wm = (warp & 1) * 32;
    const int wn = (warp >> 1) * 16;
    const int sp = blockIdx.x;      // K split 0..3
    const int bh = blockIdx.y;      // 0..63
    const int b = bh >> 3, h = bh & 7;

    const __half* ka = kh + (size_t)(b * HID + h * 64) * LDIM + sp * 1024;
    const __half* va = v  + (size_t)(b * HID + h * 64) * LDIM + sp * 1024;

    const uint32_t aOff = (uint32_t)((lane & 15) * CTX_ROWB + (lane >> 4) * 16);
    const uint32_t bOff = (uint32_t)(((lane & 7) + ((lane >> 4) << 3)) * CTX_ROWB
                                     + (((lane >> 3) & 1) * 16));

    float acc[2][2][4] = {};

    auto load_chunk = [&](int c, int buf) {
        const int k0 = c * 64;
        const uint32_t base = sb + (uint32_t)buf * CTX_STAGE;
        #pragma unroll
        for (int i = 0; i < 4; i++) {
            const int idx = t + i * 256;   // 0..1023
            const int mat = idx >> 9;      // 0=k, 1=v
            const int rr = (idx >> 3) & 63;
            const int s = idx & 7;
            const uint32_t dst = base + (uint32_t)(mat * CTX_MAT + rr * CTX_ROWB + s * 16);
            const __half* src = (mat == 0 ? ka : va) + (size_t)rr * LDIM + k0 + s * 8;
            cp_async16(dst, src);
        }
    };

    load_chunk(0, 0); cp_commit();

    for (int c = 0; c < 16; c++) {
        if (c < 15) { load_chunk(c + 1, (c + 1) & 1); cp_commit(); cp_wait1(); }
        else        { cp_wait0(); }
        __syncthreads();

        const uint32_t base = sb + (uint32_t)(c & 1) * CTX_STAGE;
        #pragma unroll
        for (int ks = 0; ks < 4; ks++) {
            const uint32_t kb = (uint32_t)(ks * 32);
            uint32_t a[2][4];
            #pragma unroll
            for (int mt = 0; mt < 2; mt++)
                ldsm_x4(a[mt], base + (uint32_t)((wm + mt * 16) * CTX_ROWB) + aOff + kb);
            uint32_t r4[4];
            ldsm_x4(r4, base + CTX_MAT + (uint32_t)(wn * CTX_ROWB) + bOff + kb);
            uint32_t bf[2][2] = {{r4[0], r4[1]}, {r4[2], r4[3]}};
            #pragma unroll
            for (int mt = 0; mt < 2; mt++)
                #pragma unroll
                for (int nt = 0; nt < 2; nt++)
                    mma_fp16(acc[mt][nt], a[mt], bf[nt]);
        }
        __syncthreads();
    }

    float* pp = part + (size_t)(sp * 64 + bh) * (DIMH * DIMH);
    #pragma unroll
    for (int mt = 0; mt < 2; mt++) {
        const int row = wm + mt * 16 + (lane >> 2);
        #pragma unroll
        for (int nt = 0; nt < 2; nt++) {
            const int col = wn + nt * 8 + 2 * (lane & 3);
            *(float2*)(pp + (size_t)row * 64 + col)
                = make_float2(acc[mt][nt][0], acc[mt][nt][1]);
            *(float2*)(pp + (size_t)(row + 8) * 64 + col)
                = make_float2(acc[mt][nt][2], acc[mt][nt][3]);
        }
    }
}

__global__ __launch_bounds__(256)
void ctx_reduce4(const float* __restrict__ part, float* __restrict__ ctx)
{
    const int i = blockIdx.x * 1024 + threadIdx.x * 4;
    float4 s = *(const float4*)(part + i);
    #pragma unroll
    for (int c = 1; c < 4; c++) {
        float4 p = *(const float4*)(part + (size_t)c * 64 * DIMH * DIMH + i);
        s.x += p.x; s.y += p.y; s.z += p.z; s.w += p.w;
    }
    *(float4*)(ctx + i) = s;
}

// ---------------------------------------------------------------------------
// Conversions
// ---------------------------------------------------------------------------
__global__ __launch_bounds__(256)
void conv_wsplit(const float* __restrict__ in, __half* __restrict__ hi,
                 __half* __restrict__ lo, int n)
{
    int i = blockIdx.x * 256 + threadIdx.x;
    if (i >= n) return;
    float v = in[i] * 64.0f;
    __half h = __float2half_rn(v);
    hi[i] = h;
    lo[i] = __float2half_rn(v - __half2float(h));
}

__global__ __launch_bounds__(256)
void conv_xT(const float* __restrict__ x, __half* __restrict__ xh)
{
    __shared__ float tile[32][33];
    const int l0 = blockIdx.x * 32, c0 = blockIdx.y * 32, b = blockIdx.z;
    const float* xb = x + (size_t)b * CDIM * LDIM;
    const int tr = threadIdx.x >> 5;
    const int tc = threadIdx.x & 31;

    #pragma unroll
    for (int i = 0; i < 4; i++) {
        const int c = tr + i * 8;
        tile[c][tc] = xb[(size_t)(c0 + c) * LDIM + l0 + tc];
    }
    __syncthreads();

    __half* oh = xh + (size_t)b * LDIM * CDIM;
    #pragma unroll
    for (int i = 0; i < 4; i++) {
        const int l = tr + i * 8;
        oh[(size_t)(l0 + l) * CDIM + c0 + tc] = __float2half_rn(tile[tc][l]);
    }
}

// ---------------------------------------------------------------------------
// softmax over L, fp32 in -> fp16 out
// ---------------------------------------------------------------------------
__global__ __launch_bounds__(256)
void softmax_k(const float* __restrict__ kin, __half* __restrict__ kout)
{
    const size_t off = (size_t)blockIdx.y * (HID * LDIM) + (size_t)blockIdx.x * LDIM;
    const float* p = kin + off;
    __half* q = kout + off;
    const int t = threadIdx.x;

    float buf[16];
    float m = -1e30f;
    #pragma unroll
    for (int c = 0; c < 4; c++) {
        float4 v = *(const float4*)(p + c * 1024 + t * 4);
        buf[c * 4 + 0] = v.x; buf[c * 4 + 1] = v.y;
        buf[c * 4 + 2] = v.z; buf[c * 4 + 3] = v.w;
        m = fmaxf(m, fmaxf(fmaxf(v.x, v.y), fmaxf(v.z, v.w)));
    }

    __shared__ float redmax[8];
    __shared__ float redsum[8];

    #pragma unroll
    for (int o = 16; o; o >>= 1) m = fmaxf(m, __shfl_xor_sync(0xffffffffu, m, o));
    if ((t & 31) == 0) redmax[t >> 5] = m;
    __syncthreads();
    m = redmax[0];
    #pragma unroll
    for (int i = 1; i < 8; i++) m = fmaxf(m, redmax[i]);

    float s = 0.0f;
    #pragma unroll
    for (int i = 0; i < 16; i++) { buf[i] = expf(buf[i] - m); s += buf[i]; }

    #pragma unroll
    for (int o = 16; o; o >>= 1) s += __shfl_xor_sync(0xffffffffu, s, o);
    if ((t & 31) == 0) redsum[t >> 5] = s;
    __syncthreads();
    s = 0.0f;
    #pragma unroll
    for (int i = 0; i < 8; i++) s += redsum[i];
    const float inv = 1.0f / s;

    #pragma unroll
    for (int c = 0; c < 4; c++) {
        __half2 h0 = __halves2half2(__float2half_rn(buf[c * 4 + 0] * inv),
                                    __float2half_rn(buf[c * 4 + 1] * inv));
        __half2 h1 = __halves2half2(__float2half_rn(buf[c * 4 + 2] * inv),
                                    __float2half_rn(buf[c * 4 + 3] * inv));
        *(__half2*)(q + c * 1024 + t * 4)     = h0;
        *(__half2*)(q + c * 1024 + t * 4 + 2) = h1;
    }
}

// ---------------------------------------------------------------------------
// make_Ab: A_bT[c][(h,e)] = sum_d ctx[b,h,d,e] * W_q[(h,d),c] -> fp16
// ---------------------------------------------------------------------------
__global__ __launch_bounds__(256)
void make_Ab(const float* __restrict__ ctx, const float* __restrict__ w_qkv,
             __half* __restrict__ Abt)
{
    const int cc = blockIdx.x;
    const int bh = blockIdx.y;
    const int b = bh >> 3, h = bh & 7;

    __shared__ float Cs[64 * 64];
    __shared__ float Ws[64][65];

    const int t = threadIdx.x;
    const float* cp = ctx + (size_t)bh * (DIMH * DIMH);
    for (int i = t; i < 4096; i += 256) Cs[i] = cp[i];
    for (int i = t; i < 4096; i += 256) {
        const int d = i >> 6, c = i & 63;
        Ws[d][c] = w_qkv[(size_t)(h * 64 + d) * CDIM + cc * 64 + c];
    }
    __syncthreads();

    for (int i = t; i < 4096; i += 256) {
        const int c = i >> 6, e = i & 63;
        float s = 0.0f;
        #pragma unroll 8
        for (int d = 0; d < 64; d++) s = fmaf(Cs[d * 64 + e], Ws[d][c], s);
        Abt[(size_t)b * (CDIM * HID) + (size_t)(cc * 64 + c) * HID + h * 64 + e]
            = __float2half_rn(s);
    }
}

// ---------------------------------------------------------------------------
// Launch
// ---------------------------------------------------------------------------
extern "C" void kernel_launch(void* const* d_in, const int* in_sizes, int n_in,
                              void* d_out, int out_size)
{
    const float* x     = (const float*)d_in[0];
    const float* w_qkv = (const float*)d_in[1];
    const float* w_out = (const float*)d_in[2];
    const float* b_out = (const float*)d_in[3];
    float* out = (float*)d_out;

    float *k32, *part, *ctx;
    __half *kh, *v16, *xT, *wkh, *wkl, *woh, *wol, *Abt, *Mbh, *Mbl;
    cudaGetSymbolAddress((void**)&k32,  g_k);
    cudaGetSymbolAddress((void**)&kh,   g_kh);
    cudaGetSymbolAddress((void**)&v16,  g_v);
    cudaGetSymbolAddress((void**)&part, g_part);
    cudaGetSymbolAddress((void**)&ctx,  g_ctx);
    cudaGetSymbolAddress((void**)&xT,   g_xT);
    cudaGetSymbolAddress((void**)&wkh,  g_wk_h);
    cudaGetSymbolAddress((void**)&wkl,  g_wk_l);
    cudaGetSymbolAddress((void**)&woh,  g_wo_h);
    cudaGetSymbolAddress((void**)&wol,  g_wo_l);
    cudaGetSymbolAddress((void**)&Abt,  g_Abt);
    cudaGetSymbolAddress((void**)&Mbh,  g_Mb_h);
    cudaGetSymbolAddress((void**)&Mbl,  g_Mb_l);

    cudaFuncSetAttribute(tc2<0>, cudaFuncAttributeMaxDynamicSharedMemorySize, TC_SMEM);
    cudaFuncSetAttribute(tc2<1>, cudaFuncAttributeMaxDynamicSharedMemorySize, TC_SMEM);
    cudaFuncSetAttribute(tc2<2>, cudaFuncAttributeMaxDynamicSharedMemorySize, TC_SMEM);

    const dim3 blk(256);
    const dim3 blk512(512);
    const long sX  = (long)CDIM * LDIM;
    const long sXT = (long)LDIM * CDIM;
    const long sK  = (long)HID * LDIM;

    // 0) conversions
    conv_wsplit<<<(2 * HID * CDIM + 255) / 256, blk>>>(
        w_qkv + (size_t)HID * CDIM, wkh, wkl, 2 * HID * CDIM);
    conv_wsplit<<<(CDIM * HID + 255) / 256, blk>>>(w_out, woh, wol, CDIM * HID);
    conv_xT<<<dim3(LDIM / 32, CDIM / 32, BATCH), blk>>>(x, xT);

    // 1) GEMM1: k (fp32) + v (fp16) = W_kv @ x_b
    tc2<2><<<dim3(LDIM / 256, (2 * HID) / 128, BATCH), blk512, TC_SMEM>>>(
        wkh, wkl, 0L, xT, sXT, k32, v16, nullptr,
        sK, LDIM, nullptr, 1.0f / 64.0f, 0.0f);

    // 2) softmax: k fp32 -> k̂ fp16
    softmax_k<<<dim3(HID, BATCH), blk>>>(k32, kh);

    // 3) context (tensor core, split-K 4) + reduce
    context_mma<<<dim3(4, 64), blk>>>(kh, v16, part);
    ctx_reduce4<<<(64 * DIMH * DIMH) / 1024, blk>>>(part, ctx);

    // 4) A_b^T fp16
    make_Ab<<<dim3(8, 64), blk>>>(ctx, w_qkv, Abt);

    // 5) M_b = w_out @ A_b -> fp16 split of 2048*M_b
    tc2<1><<<dim3(CDIM / 256, CDIM / 128, BATCH), blk512, TC_SMEM>>>(
        woh, wol, 0L, Abt, (long)CDIM * HID, nullptr, Mbh, Mbl,
        (long)CDIM * CDIM, CDIM, nullptr, 0.0f, 32.0f);

    // 6) out = M_b @ x_b + b_out
    tc2<0><<<dim3(LDIM / 256, CDIM / 128, BATCH), blk512, TC_SMEM>>>(
        Mbh, Mbl, (long)CDIM * CDIM, xT, sXT, out, nullptr, nullptr,
        sX, LDIM, b_out, 1.0f / 2048.0f, 0.0f);
}

// round 7
// speedup vs baseline: 1.2095x; 1.2095x over previous
#include <cuda_runtime.h>
#include <cuda_fp16.h>
#include <math.h>
#include <stdint.h>

// Problem constants
#define BATCH 8
#define CDIM  512
#define LDIM  4096
#define HEADS 8
#define DIMH  64
#define HID   512   // HEADS*DIMH

// ---------------------------------------------------------------------------
// Scratch (static __device__ arrays)
// ---------------------------------------------------------------------------
__device__ float  g_k  [(size_t)BATCH * HID * LDIM];      // fp32 k logits
__device__ __half g_kh [(size_t)BATCH * HID * LDIM];      // fp16 softmaxed k
__device__ __half g_v  [(size_t)BATCH * HID * LDIM];      // fp16 v
__device__ float  g_part[(size_t)4 * 64 * DIMH * DIMH];   // context split-K partials
__device__ float  g_ctx [(size_t)64 * DIMH * DIMH];       // context [bh][d*64+e]

__device__ __half g_xT  [(size_t)BATCH * LDIM * CDIM];    // fp16(x)^T [b][l][c]
__device__ __half g_wk  [(size_t)(2 * HID) * CDIM];       // fp16(64*W_kv) (1-term)
__device__ __half g_wo_h[(size_t)CDIM * HID];             // fp16(64*W_out) hi
__device__ __half g_wo_l[(size_t)CDIM * HID];
__device__ __half g_Abt [(size_t)BATCH * CDIM * HID];     // fp16(A_b^T) [b][c][hid]
__device__ __half g_Mb_h[(size_t)BATCH * CDIM * CDIM];    // fp16(2048*M_b) hi
__device__ __half g_Mb_l[(size_t)BATCH * CDIM * CDIM];    // lo

// ---------------------------------------------------------------------------
// PTX helpers
// ---------------------------------------------------------------------------
__device__ __forceinline__ uint32_t smem_u32(const void* p) {
    uint32_t a;
    asm("{ .reg .u64 t; cvta.to.shared.u64 t, %1; cvt.u32.u64 %0, t; }" : "=r"(a) : "l"(p));
    return a;
}
__device__ __forceinline__ void cp_async16(uint32_t dst, const void* src) {
    asm volatile("cp.async.cg.shared.global [%0], [%1], 16;" :: "r"(dst), "l"(src));
}
__device__ __forceinline__ void cp_commit() { asm volatile("cp.async.commit_group;" ::: "memory"); }
__device__ __forceinline__ void cp_wait1()  { asm volatile("cp.async.wait_group 1;" ::: "memory"); }
__device__ __forceinline__ void cp_wait0()  { asm volatile("cp.async.wait_group 0;" ::: "memory"); }
__device__ __forceinline__ void ldsm_x4(uint32_t* r, uint32_t addr) {
    asm volatile("ldmatrix.sync.aligned.m8n8.x4.shared.b16 {%0,%1,%2,%3}, [%4];"
                 : "=r"(r[0]), "=r"(r[1]), "=r"(r[2]), "=r"(r[3]) : "r"(addr));
}
__device__ __forceinline__ void mma_fp16(float* c, const uint32_t* a, const uint32_t* b) {
    asm volatile(
        "mma.sync.aligned.m16n8k16.row.col.f32.f16.f16.f32 "
        "{%0,%1,%2,%3}, {%4,%5,%6,%7}, {%8,%9}, {%0,%1,%2,%3};"
        : "+f"(c[0]), "+f"(c[1]), "+f"(c[2]), "+f"(c[3])
        : "r"(a[0]), "r"(a[1]), "r"(a[2]), "r"(a[3]), "r"(b[0]), "r"(b[1]));
}

// ---------------------------------------------------------------------------
// tc2: C[b][m][n] = sum_k (Ah [+Al])[m,k] * Bh[n,k]  (TERMS-term fp16, K=512)
// CTA tile 128x256, K-chunk 64, 3-stage cp.async pipeline,
// 256 threads = 8 warps (2Mx4N), warp tile 64x64.
// MODE 0: fp32 out = acc*invScale (+bias)
// MODE 1: fp16 hi/lo split of acc*hScale
// MODE 2: GEMM1 — m0<512 writes fp32 k; m0>=512 writes fp16 v at row-512.
// ---------------------------------------------------------------------------
#define ROWB   144
#define A_MAT  (128 * ROWB)          // 18432
#define B_MAT  (256 * ROWB)          // 36864
#define TC_SMEM1 (3 * (A_MAT + B_MAT))      // 165888 (TERMS=1)
#define TC_SMEM2 (3 * (2 * A_MAT + B_MAT))  // 221184 (TERMS=2)

template<int MODE, int TERMS>
__global__ __launch_bounds__(256, 1)
void tc2(const __half* __restrict__ Ah, const __half* __restrict__ Al, long aBatch,
         const __half* __restrict__ Bh, long bBatch,
         float* __restrict__ Cf, __half* __restrict__ Ch, __half* __restrict__ Cl,
         long cBatch, int cRow,
         const float* __restrict__ bias, float invScale, float hScale)
{
    constexpr uint32_t STG = (uint32_t)(TERMS * A_MAT + B_MAT);
    constexpr uint32_t BOFS = (uint32_t)(TERMS * A_MAT);

    extern __shared__ char smem[];
    const uint32_t sb = smem_u32(smem);
    const int t = threadIdx.x;
    const int lane = t & 31;
    const int warp = t >> 5;
    const int wm = (warp & 1) * 64;
    const int wn = (warp >> 1) * 64;
    const int n0 = blockIdx.x * 256;
    const int m0 = blockIdx.y * 128;
    const int b = blockIdx.z;

    Ah += (size_t)b * aBatch;
    if (TERMS == 2) Al += (size_t)b * aBatch;
    Bh += (size_t)b * bBatch;

    const uint32_t aOff = (uint32_t)((lane & 15) * ROWB + (lane >> 4) * 16);
    const uint32_t bOff = (uint32_t)(((lane & 7) + ((lane >> 4) << 3)) * ROWB
                                     + (((lane >> 3) & 1) * 16));

    float acc[4][8][4] = {};

    auto load_chunk = [&](int c, int buf) {
        const int k0 = c * 64;
        const uint32_t base = sb + (uint32_t)buf * STG;
        #pragma unroll
        for (int i = 0; i < 4; i++) {
            const int idx = t + i * 256;
            const int r = idx >> 3, s = idx & 7;
            const uint32_t dst = base + (uint32_t)(r * ROWB + s * 16);
            const size_t ga = (size_t)(m0 + r) * 512 + k0 + s * 8;
            cp_async16(dst, Ah + ga);
            if (TERMS == 2) cp_async16(dst + A_MAT, Al + ga);
        }
        #pragma unroll
        for (int i = 0; i < 8; i++) {
            const int idx = t + i * 256;
            const int r = idx >> 3, s = idx & 7;
            const uint32_t dst = base + BOFS + (uint32_t)(r * ROWB + s * 16);
            cp_async16(dst, Bh + (size_t)(n0 + r) * 512 + k0 + s * 8);
        }
    };

    load_chunk(0, 0); cp_commit();
    load_chunk(1, 1); cp_commit();

    for (int c = 0; c < 8; c++) {
        if (c < 7) cp_wait1(); else cp_wait0();
        __syncthreads();
        if (c < 6) { load_chunk(c + 2, (c + 2) % 3); cp_commit(); }

        const uint32_t base = sb + (uint32_t)(c % 3) * STG;
        #pragma unroll
        for (int ks = 0; ks < 4; ks++) {
            const uint32_t kb = (uint32_t)(ks * 32);
            uint32_t ah[4][4], al[4][4];
            #pragma unroll
            for (int mt = 0; mt < 4; mt++) {
                const uint32_t ra = base + (uint32_t)((wm + mt * 16) * ROWB) + aOff + kb;
                ldsm_x4(ah[mt], ra);
                if (TERMS == 2) ldsm_x4(al[mt], ra + A_MAT);
            }
            uint32_t bfr[8][2];
            #pragma unroll
            for (int np = 0; np < 4; np++) {
                uint32_t r4[4];
                const uint32_t rb = base + BOFS
                    + (uint32_t)((wn + np * 16) * ROWB) + bOff + kb;
                ldsm_x4(r4, rb);
                bfr[np * 2][0] = r4[0]; bfr[np * 2][1] = r4[1];
                bfr[np * 2 + 1][0] = r4[2]; bfr[np * 2 + 1][1] = r4[3];
            }
            #pragma unroll
            for (int mt = 0; mt < 4; mt++)
                #pragma unroll
                for (int nt = 0; nt < 8; nt++) {
                    mma_fp16(acc[mt][nt], ah[mt], bfr[nt]);
                    if (TERMS == 2) mma_fp16(acc[mt][nt], al[mt], bfr[nt]);
                }
        }
        __syncthreads();
    }

    // ---- epilogue ----
    #pragma unroll
    for (int mt = 0; mt < 4; mt++) {
        const int row = m0 + wm + mt * 16 + (lane >> 2);
        float bv0 = 0.0f, bv1 = 0.0f;
        if (MODE == 0 && bias) { bv0 = bias[row]; bv1 = bias[row + 8]; }
        #pragma unroll
        for (int nt = 0; nt < 8; nt++) {
            const int col = n0 + wn + nt * 8 + 2 * (lane & 3);
            if (MODE == 0) {
                float* c0 = Cf + (size_t)b * cBatch + (size_t)row * cRow + col;
                float* c1 = Cf + (size_t)b * cBatch + (size_t)(row + 8) * cRow + col;
                *(float2*)c0 = make_float2(acc[mt][nt][0] * invScale + bv0,
                                           acc[mt][nt][1] * invScale + bv0);
                *(float2*)c1 = make_float2(acc[mt][nt][2] * invScale + bv1,
                                           acc[mt][nt][3] * invScale + bv1);
            } else if (MODE == 1) {
                #pragma unroll
                for (int hf = 0; hf < 2; hf++) {
                    const int rr = row + hf * 8;
                    const float v0 = acc[mt][nt][hf * 2 + 0] * hScale;
                    const float v1 = acc[mt][nt][hf * 2 + 1] * hScale;
                    const __half h0 = __float2half_rn(v0);
                    const __half h1 = __float2half_rn(v1);
                    const __half l0 = __float2half_rn(v0 - __half2float(h0));
                    const __half l1 = __float2half_rn(v1 - __half2float(h1));
                    const size_t o = (size_t)b * cBatch + (size_t)rr * cRow + col;
                    *(__half2*)(Ch + o) = __halves2half2(h0, h1);
                    *(__half2*)(Cl + o) = __halves2half2(l0, l1);
                }
            } else {  // MODE 2
                if (m0 < 512) {
                    float* c0 = Cf + (size_t)b * cBatch + (size_t)row * cRow + col;
                    float* c1 = Cf + (size_t)b * cBatch + (size_t)(row + 8) * cRow + col;
                    *(float2*)c0 = make_float2(acc[mt][nt][0] * invScale,
                                               acc[mt][nt][1] * invScale);
                    *(float2*)c1 = make_float2(acc[mt][nt][2] * invScale,
                                               acc[mt][nt][3] * invScale);
                } else {
                    #pragma unroll
                    for (int hf = 0; hf < 2; hf++) {
                        const int rr = row - 512 + hf * 8;
                        const float v0 = acc[mt][nt][hf * 2 + 0] * invScale;
                        const float v1 = acc[mt][nt][hf * 2 + 1] * invScale;
                        const size_t o = (size_t)b * cBatch + (size_t)rr * cRow + col;
                        *(__half2*)(Ch + o) =
                            __halves2half2(__float2half_rn(v0), __float2half_rn(v1));
                    }
                }
            }
        }
    }
}

// ---------------------------------------------------------------------------
// context_mma: part[sp][bh][d][e] = sum_{n in split sp} kh[d,n] * v[e,n]
// ---------------------------------------------------------------------------
#define CTX_ROWB 144
#define CTX_MAT  (64 * CTX_ROWB)
#define CTX_STAGE (2 * CTX_MAT)

__global__ __launch_bounds__(256)
void context_mma(const __half* __restrict__ kh, const __half* __restrict__ v,
                 float* __restrict__ part)
{
    __shared__ __align__(16) char smem[2 * CTX_STAGE];
    const uint32_t sb = smem_u32(smem);
    const int t = threadIdx.x;
    const int lane = t & 31;
    const int warp = t >> 5;
    const int wm = (warp & 1) * 32;
    const int wn = (warp >> 1) * 16;
    const int sp = blockIdx.x;
    const int bh = blockIdx.y;
    const int b = bh >> 3, h = bh & 7;

    const __half* ka = kh + (size_t)(b * HID + h * 64) * LDIM + sp * 1024;
    const __half* va = v  + (size_t)(b * HID + h * 64) * LDIM + sp * 1024;

    const uint32_t aOff = (uint32_t)((lane & 15) * CTX_ROWB + (lane >> 4) * 16);
    const uint32_t bOff = (uint32_t)(((lane & 7) + ((lane >> 4) << 3)) * CTX_ROWB
                                     + (((lane >> 3) & 1) * 16));

    float acc[2][2][4] = {};

    auto load_chunk = [&](int c, int buf) {
        const int k0 = c * 64;
        const uint32_t base = sb + (uint32_t)buf * CTX_STAGE;
        #pragma unroll
        for (int i = 0; i < 4; i++) {
            const int idx = t + i * 256;
            const int mat = idx >> 9;
            const int rr = (idx >> 3) & 63;
            const int s = idx & 7;
            const uint32_t dst = base + (uint32_t)(mat * CTX_MAT + rr * CTX_ROWB + s * 16);
            const __half* src = (mat == 0 ? ka : va) + (size_t)rr * LDIM + k0 + s * 8;
            cp_async16(dst, src);
        }
    };

    load_chunk(0, 0); cp_commit();

    for (int c = 0; c < 16; c++) {
        if (c < 15) { load_chunk(c + 1, (c + 1) & 1); cp_commit(); cp_wait1(); }
        else        { cp_wait0(); }
        __syncthreads();

        const uint32_t base = sb + (uint32_t)(c & 1) * CTX_STAGE;
        #pragma unroll
        for (int ks = 0; ks < 4; ks++) {
            const uint32_t kb = (uint32_t)(ks * 32);
            uint32_t a[2][4];
            #pragma unroll
            for (int mt = 0; mt < 2; mt++)
                ldsm_x4(a[mt], base + (uint32_t)((wm + mt * 16) * CTX_ROWB) + aOff + kb);
            uint32_t r4[4];
            ldsm_x4(r4, base + CTX_MAT + (uint32_t)(wn * CTX_ROWB) + bOff + kb);
            uint32_t bf[2][2] = {{r4[0], r4[1]}, {r4[2], r4[3]}};
            #pragma unroll
            for (int mt = 0; mt < 2; mt++)
                #pragma unroll
                for (int nt = 0; nt < 2; nt++)
                    mma_fp16(acc[mt][nt], a[mt], bf[nt]);
        }
        __syncthreads();
    }

    float* pp = part + (size_t)(sp * 64 + bh) * (DIMH * DIMH);
    #pragma unroll
    for (int mt = 0; mt < 2; mt++) {
        const int row = wm + mt * 16 + (lane >> 2);
        #pragma unroll
        for (int nt = 0; nt < 2; nt++) {
            const int col = wn + nt * 8 + 2 * (lane & 3);
            *(float2*)(pp + (size_t)row * 64 + col)
                = make_float2(acc[mt][nt][0], acc[mt][nt][1]);
            *(float2*)(pp + (size_t)(row + 8) * 64 + col)
                = make_float2(acc[mt][nt][2], acc[mt][nt][3]);
        }
    }
}

__global__ __launch_bounds__(256)
void ctx_reduce4(const float* __restrict__ part, float* __restrict__ ctx)
{
    const int i = blockIdx.x * 1024 + threadIdx.x * 4;
    float4 s = *(const float4*)(part + i);
    #pragma unroll
    for (int c = 1; c < 4; c++) {
        float4 p = *(const float4*)(part + (size_t)c * 64 * DIMH * DIMH + i);
        s.x += p.x; s.y += p.y; s.z += p.z; s.w += p.w;
    }
    *(float4*)(ctx + i) = s;
}

// ---------------------------------------------------------------------------
// Conversions
// ---------------------------------------------------------------------------
__global__ __launch_bounds__(256)
void conv_w1(const float* __restrict__ in, __half* __restrict__ hi, int n)
{
    int i = blockIdx.x * 256 + threadIdx.x;
    if (i >= n) return;
    hi[i] = __float2half_rn(in[i] * 64.0f);
}

__global__ __launch_bounds__(256)
void conv_wsplit(const float* __restrict__ in, __half* __restrict__ hi,
                 __half* __restrict__ lo, int n)
{
    int i = blockIdx.x * 256 + threadIdx.x;
    if (i >= n) return;
    float v = in[i] * 64.0f;
    __half h = __float2half_rn(v);
    hi[i] = h;
    lo[i] = __float2half_rn(v - __half2float(h));
}

__global__ __launch_bounds__(256)
void conv_xT(const float* __restrict__ x, __half* __restrict__ xh)
{
    __shared__ float tile[32][33];
    const int l0 = blockIdx.x * 32, c0 = blockIdx.y * 32, b = blockIdx.z;
    const float* xb = x + (size_t)b * CDIM * LDIM;
    const int tr = threadIdx.x >> 5;
    const int tc = threadIdx.x & 31;

    #pragma unroll
    for (int i = 0; i < 4; i++) {
        const int c = tr + i * 8;
        tile[c][tc] = xb[(size_t)(c0 + c) * LDIM + l0 + tc];
    }
    __syncthreads();

    __half* oh = xh + (size_t)b * LDIM * CDIM;
    #pragma unroll
    for (int i = 0; i < 4; i++) {
        const int l = tr + i * 8;
        oh[(size_t)(l0 + l) * CDIM + c0 + tc] = __float2half_rn(tile[tc][l]);
    }
}

// ---------------------------------------------------------------------------
// softmax over L, fp32 in -> fp16 out
// ---------------------------------------------------------------------------
__global__ __launch_bounds__(256)
void softmax_k(const float* __restrict__ kin, __half* __restrict__ kout)
{
    const size_t off = (size_t)blockIdx.y * (HID * LDIM) + (size_t)blockIdx.x * LDIM;
    const float* p = kin + off;
    __half* q = kout + off;
    const int t = threadIdx.x;

    float buf[16];
    float m = -1e30f;
    #pragma unroll
    for (int c = 0; c < 4; c++) {
        float4 v = *(const float4*)(p + c * 1024 + t * 4);
        buf[c * 4 + 0] = v.x; buf[c * 4 + 1] = v.y;
        buf[c * 4 + 2] = v.z; buf[c * 4 + 3] = v.w;
        m = fmaxf(m, fmaxf(fmaxf(v.x, v.y), fmaxf(v.z, v.w)));
    }

    __shared__ float redmax[8];
    __shared__ float redsum[8];

    #pragma unroll
    for (int o = 16; o; o >>= 1) m = fmaxf(m, __shfl_xor_sync(0xffffffffu, m, o));
    if ((t & 31) == 0) redmax[t >> 5] = m;
    __syncthreads();
    m = redmax[0];
    #pragma unroll
    for (int i = 1; i < 8; i++) m = fmaxf(m, redmax[i]);

    float s = 0.0f;
    #pragma unroll
    for (int i = 0; i < 16; i++) { buf[i] = expf(buf[i] - m); s += buf[i]; }

    #pragma unroll
    for (int o = 16; o; o >>= 1) s += __shfl_xor_sync(0xffffffffu, s, o);
    if ((t & 31) == 0) redsum[t >> 5] = s;
    __syncthreads();
    s = 0.0f;
    #pragma unroll
    for (int i = 0; i < 8; i++) s += redsum[i];
    const float inv = 1.0f / s;

    #pragma unroll
    for (int c = 0; c < 4; c++) {
        __half2 h0 = __halves2half2(__float2half_rn(buf[c * 4 + 0] * inv),
                                    __float2half_rn(buf[c * 4 + 1] * inv));
        __half2 h1 = __halves2half2(__float2half_rn(buf[c * 4 + 2] * inv),
                                    __float2half_rn(buf[c * 4 + 3] * inv));
        *(__half2*)(q + c * 1024 + t * 4)     = h0;
        *(__half2*)(q + c * 1024 + t * 4 + 2) = h1;
    }
}

// ---------------------------------------------------------------------------
// make_Ab: A_bT[c][(h,e)] = sum_d ctx[b,h,d,e] * W_q[(h,d),c] -> fp16
// ---------------------------------------------------------------------------
__global__ __launch_bounds__(256)
void make_Ab(const float* __restrict__ ctx, const float* __restrict__ w_qkv,
             __half* __restrict__ Abt)
{
    const int cc = blockIdx.x;
    const int bh = blockIdx.y;
    const int b = bh >> 3, h = bh & 7;

    __shared__ float Cs[64 * 64];
    __shared__ float Ws[64][65];

    const int t = threadIdx.x;
    const float* cp = ctx + (size_t)bh * (DIMH * DIMH);
    for (int i = t; i < 4096; i += 256) Cs[i] = cp[i];
    for (int i = t; i < 4096; i += 256) {
        const int d = i >> 6, c = i & 63;
        Ws[d][c] = w_qkv[(size_t)(h * 64 + d) * CDIM + cc * 64 + c];
    }
    __syncthreads();

    for (int i = t; i < 4096; i += 256) {
        const int c = i >> 6, e = i & 63;
        float s = 0.0f;
        #pragma unroll 8
        for (int d = 0; d < 64; d++) s = fmaf(Cs[d * 64 + e], Ws[d][c], s);
        Abt[(size_t)b * (CDIM * HID) + (size_t)(cc * 64 + c) * HID + h * 64 + e]
            = __float2half_rn(s);
    }
}

// ---------------------------------------------------------------------------
// Launch
// ---------------------------------------------------------------------------
extern "C" void kernel_launch(void* const* d_in, const int* in_sizes, int n_in,
                              void* d_out, int out_size)
{
    const float* x     = (const float*)d_in[0];
    const float* w_qkv = (const float*)d_in[1];
    const float* w_out = (const float*)d_in[2];
    const float* b_out = (const float*)d_in[3];
    float* out = (float*)d_out;

    float *k32, *part, *ctx;
    __half *kh, *v16, *xT, *wk, *woh, *wol, *Abt, *Mbh, *Mbl;
    cudaGetSymbolAddress((void**)&k32,  g_k);
    cudaGetSymbolAddress((void**)&kh,   g_kh);
    cudaGetSymbolAddress((void**)&v16,  g_v);
    cudaGetSymbolAddress((void**)&part, g_part);
    cudaGetSymbolAddress((void**)&ctx,  g_ctx);
    cudaGetSymbolAddress((void**)&xT,   g_xT);
    cudaGetSymbolAddress((void**)&wk,   g_wk);
    cudaGetSymbolAddress((void**)&woh,  g_wo_h);
    cudaGetSymbolAddress((void**)&wol,  g_wo_l);
    cudaGetSymbolAddress((void**)&Abt,  g_Abt);
    cudaGetSymbolAddress((void**)&Mbh,  g_Mb_h);
    cudaGetSymbolAddress((void**)&Mbl,  g_Mb_l);

    cudaFuncSetAttribute((const void*)tc2<2, 1>, cudaFuncAttributeMaxDynamicSharedMemorySize, TC_SMEM1);
    cudaFuncSetAttribute((const void*)tc2<1, 2>, cudaFuncAttributeMaxDynamicSharedMemorySize, TC_SMEM2);
    cudaFuncSetAttribute((const void*)tc2<0, 2>, cudaFuncAttributeMaxDynamicSharedMemorySize, TC_SMEM2);

    const dim3 blk(256);
    const long sX  = (long)CDIM * LDIM;
    const long sXT = (long)LDIM * CDIM;
    const long sK  = (long)HID * LDIM;

    // 0) conversions
    conv_w1<<<(2 * HID * CDIM + 255) / 256, blk>>>(
        w_qkv + (size_t)HID * CDIM, wk, 2 * HID * CDIM);
    conv_wsplit<<<(CDIM * HID + 255) / 256, blk>>>(w_out, woh, wol, CDIM * HID);
    conv_xT<<<dim3(LDIM / 32, CDIM / 32, BATCH), blk>>>(x, xT);

    // 1) GEMM1 (1-term fp16): k (fp32) + v (fp16) = W_kv @ x_b
    tc2<2, 1><<<dim3(LDIM / 256, (2 * HID) / 128, BATCH), blk, TC_SMEM1>>>(
        wk, nullptr, 0L, xT, sXT, k32, v16, nullptr,
        sK, LDIM, nullptr, 1.0f / 64.0f, 0.0f);

    // 2) softmax: k fp32 -> k̂ fp16
    softmax_k<<<dim3(HID, BATCH), blk>>>(k32, kh);

    // 3) context (tensor core, split-K 4) + reduce
    context_mma<<<dim3(4, 64), blk>>>(kh, v16, part);
    ctx_reduce4<<<(64 * DIMH * DIMH) / 1024, blk>>>(part, ctx);

    // 4) A_b^T fp16
    make_Ab<<<dim3(8, 64), blk>>>(ctx, w_qkv, Abt);

    // 5) M_b = w_out @ A_b -> fp16 split of 2048*M_b (2-term)
    tc2<1, 2><<<dim3(CDIM / 256, CDIM / 128, BATCH), blk, TC_SMEM2>>>(
        woh, wol, 0L, Abt, (long)CDIM * HID, nullptr, Mbh, Mbl,
        (long)CDIM * CDIM, CDIM, nullptr, 0.0f, 32.0f);

    // 6) out = M_b @ x_b + b_out (2-term)
    tc2<0, 2><<<dim3(LDIM / 256, CDIM / 128, BATCH), blk, TC_SMEM2>>>(
        Mbh, Mbl, (long)CDIM * CDIM, xT, sXT, out, nullptr, nullptr,
        sX, LDIM, b_out, 1.0f / 2048.0f, 0.0f);
}

// round 8
// speedup vs baseline: 1.5065x; 1.2456x over previous
#include <cuda_runtime.h>
#include <cuda_fp16.h>
#include <math.h>
#include <stdint.h>

// Problem constants
#define BATCH 8
#define CDIM  512
#define LDIM  4096
#define HEADS 8
#define DIMH  64
#define HID   512   // HEADS*DIMH

// ---------------------------------------------------------------------------
// Scratch (static __device__ arrays)
// ---------------------------------------------------------------------------
__device__ float  g_k  [(size_t)BATCH * HID * LDIM];      // fp32 k logits
__device__ __half g_kh [(size_t)BATCH * HID * LDIM];      // fp16 softmaxed k
__device__ __half g_v  [(size_t)BATCH * HID * LDIM];      // fp16 v
__device__ float  g_part[(size_t)4 * 64 * DIMH * DIMH];   // context split-K partials
__device__ float  g_ctx [(size_t)64 * DIMH * DIMH];       // context [bh][d*64+e]

__device__ __half g_xT  [(size_t)BATCH * LDIM * CDIM];    // fp16(x)^T [b][l][c]
__device__ __half g_wk  [(size_t)(2 * HID) * CDIM];       // fp16(64*W_kv)
__device__ __half g_wo_h[(size_t)CDIM * HID];             // fp16(64*W_out) hi
__device__ __half g_wo_l[(size_t)CDIM * HID];
__device__ __half g_Abt [(size_t)BATCH * CDIM * HID];     // fp16(A_b^T) [b][c][hid]
__device__ __half g_Mb_h[(size_t)BATCH * CDIM * CDIM];    // fp16(2048*M_b) hi
__device__ __half g_Mb_l[(size_t)BATCH * CDIM * CDIM];    // lo (written, unused by GEMM3)

// ---------------------------------------------------------------------------
// PTX helpers
// ---------------------------------------------------------------------------
__device__ __forceinline__ uint32_t smem_u32(const void* p) {
    uint32_t a;
    asm("{ .reg .u64 t; cvta.to.shared.u64 t, %1; cvt.u32.u64 %0, t; }" : "=r"(a) : "l"(p));
    return a;
}
__device__ __forceinline__ void cp_async16(uint32_t dst, const void* src) {
    asm volatile("cp.async.cg.shared.global [%0], [%1], 16;" :: "r"(dst), "l"(src));
}
__device__ __forceinline__ void cp_commit() { asm volatile("cp.async.commit_group;" ::: "memory"); }
__device__ __forceinline__ void cp_wait1()  { asm volatile("cp.async.wait_group 1;" ::: "memory"); }
__device__ __forceinline__ void cp_wait0()  { asm volatile("cp.async.wait_group 0;" ::: "memory"); }
__device__ __forceinline__ void ldsm_x4(uint32_t* r, uint32_t addr) {
    asm volatile("ldmatrix.sync.aligned.m8n8.x4.shared.b16 {%0,%1,%2,%3}, [%4];"
                 : "=r"(r[0]), "=r"(r[1]), "=r"(r[2]), "=r"(r[3]) : "r"(addr));
}
__device__ __forceinline__ void mma_fp16(float* c, const uint32_t* a, const uint32_t* b) {
    asm volatile(
        "mma.sync.aligned.m16n8k16.row.col.f32.f16.f16.f32 "
        "{%0,%1,%2,%3}, {%4,%5,%6,%7}, {%8,%9}, {%0,%1,%2,%3};"
        : "+f"(c[0]), "+f"(c[1]), "+f"(c[2]), "+f"(c[3])
        : "r"(a[0]), "r"(a[1]), "r"(a[2]), "r"(a[3]), "r"(b[0]), "r"(b[1]));
}

// ---------------------------------------------------------------------------
// tc2: C[b][m][n] = sum_k (Ah [+Al])[m,k] * Bh[n,k]  (TERMS-term fp16, K=512)
// CTA tile 128x128, K-chunk 64, 3-stage cp.async pipeline,
// 256 threads = 8 warps (4Mx2N), warp tile 32x64, <=128 regs -> 2 CTAs/SM.
// MODE 0: fp32 out = acc*invScale (+bias)
// MODE 1: fp16 hi/lo split of acc*hScale
// MODE 2: GEMM1 — m0<512 writes fp32 k; m0>=512 writes fp16 v at row-512.
// ---------------------------------------------------------------------------
#define ROWB   144
#define A_MAT  (128 * ROWB)          // 18432
#define B_MAT  (128 * ROWB)          // 18432
#define TC_SMEM1 (3 * (A_MAT + B_MAT))      // 110592 (TERMS=1) -> 2 CTAs/SM
#define TC_SMEM2 (3 * (2 * A_MAT + B_MAT))  // 165888 (TERMS=2) -> 1 CTA/SM

template<int MODE, int TERMS>
__global__ __launch_bounds__(256, 2)
void tc2(const __half* __restrict__ Ah, const __half* __restrict__ Al, long aBatch,
         const __half* __restrict__ Bh, long bBatch,
         float* __restrict__ Cf, __half* __restrict__ Ch, __half* __restrict__ Cl,
         long cBatch, int cRow,
         const float* __restrict__ bias, float invScale, float hScale)
{
    constexpr uint32_t STG  = (uint32_t)(TERMS * A_MAT + B_MAT);
    constexpr uint32_t BOFS = (uint32_t)(TERMS * A_MAT);

    extern __shared__ char smem[];
    const uint32_t sb = smem_u32(smem);
    const int t = threadIdx.x;
    const int lane = t & 31;
    const int warp = t >> 5;           // 0..7
    const int wm = (warp & 3) * 32;    // 4 M-tiles of 32
    const int wn = (warp >> 2) * 64;   // 2 N-tiles of 64
    const int n0 = blockIdx.x * 128;
    const int m0 = blockIdx.y * 128;
    const int b = blockIdx.z;

    Ah += (size_t)b * aBatch;
    if (TERMS == 2) Al += (size_t)b * aBatch;
    Bh += (size_t)b * bBatch;

    const uint32_t aOff = (uint32_t)((lane & 15) * ROWB + (lane >> 4) * 16);
    const uint32_t bOff = (uint32_t)(((lane & 7) + ((lane >> 4) << 3)) * ROWB
                                     + (((lane >> 3) & 1) * 16));

    float acc[2][8][4] = {};   // [mt][nt][reg]  (64 floats)

    auto load_chunk = [&](int c, int buf) {
        const int k0 = c * 64;
        const uint32_t base = sb + (uint32_t)buf * STG;
        #pragma unroll
        for (int i = 0; i < 4; i++) {            // A: 1024 segs
            const int idx = t + i * 256;
            const int r = idx >> 3, s = idx & 7;
            const uint32_t dst = base + (uint32_t)(r * ROWB + s * 16);
            const size_t ga = (size_t)(m0 + r) * 512 + k0 + s * 8;
            cp_async16(dst, Ah + ga);
            if (TERMS == 2) cp_async16(dst + A_MAT, Al + ga);
        }
        #pragma unroll
        for (int i = 0; i < 4; i++) {            // B: 1024 segs
            const int idx = t + i * 256;
            const int r = idx >> 3, s = idx & 7;
            const uint32_t dst = base + BOFS + (uint32_t)(r * ROWB + s * 16);
            cp_async16(dst, Bh + (size_t)(n0 + r) * 512 + k0 + s * 8);
        }
    };

    load_chunk(0, 0); cp_commit();
    load_chunk(1, 1); cp_commit();

    for (int c = 0; c < 8; c++) {
        if (c < 7) cp_wait1(); else cp_wait0();
        __syncthreads();
        if (c < 6) { load_chunk(c + 2, (c + 2) % 3); cp_commit(); }

        const uint32_t base = sb + (uint32_t)(c % 3) * STG;
        #pragma unroll
        for (int ks = 0; ks < 4; ks++) {
            const uint32_t kb = (uint32_t)(ks * 32);
            uint32_t ah[2][4], al[2][4];
            #pragma unroll
            for (int mt = 0; mt < 2; mt++) {
                const uint32_t ra = base + (uint32_t)((wm + mt * 16) * ROWB) + aOff + kb;
                ldsm_x4(ah[mt], ra);
                if (TERMS == 2) ldsm_x4(al[mt], ra + A_MAT);
            }
            uint32_t bfr[8][2];
            #pragma unroll
            for (int np = 0; np < 4; np++) {
                uint32_t r4[4];
                const uint32_t rb = base + BOFS
                    + (uint32_t)((wn + np * 16) * ROWB) + bOff + kb;
                ldsm_x4(r4, rb);
                bfr[np * 2][0] = r4[0]; bfr[np * 2][1] = r4[1];
                bfr[np * 2 + 1][0] = r4[2]; bfr[np * 2 + 1][1] = r4[3];
            }
            #pragma unroll
            for (int mt = 0; mt < 2; mt++)
                #pragma unroll
                for (int nt = 0; nt < 8; nt++) {
                    mma_fp16(acc[mt][nt], ah[mt], bfr[nt]);
                    if (TERMS == 2) mma_fp16(acc[mt][nt], al[mt], bfr[nt]);
                }
        }
        __syncthreads();
    }

    // ---- epilogue ----
    #pragma unroll
    for (int mt = 0; mt < 2; mt++) {
        const int row = m0 + wm + mt * 16 + (lane >> 2);
        float bv0 = 0.0f, bv1 = 0.0f;
        if (MODE == 0 && bias) { bv0 = bias[row]; bv1 = bias[row + 8]; }
        #pragma unroll
        for (int nt = 0; nt < 8; nt++) {
            const int col = n0 + wn + nt * 8 + 2 * (lane & 3);
            if (MODE == 0) {
                float* c0 = Cf + (size_t)b * cBatch + (size_t)row * cRow + col;
                float* c1 = Cf + (size_t)b * cBatch + (size_t)(row + 8) * cRow + col;
                *(float2*)c0 = make_float2(acc[mt][nt][0] * invScale + bv0,
                                           acc[mt][nt][1] * invScale + bv0);
                *(float2*)c1 = make_float2(acc[mt][nt][2] * invScale + bv1,
                                           acc[mt][nt][3] * invScale + bv1);
            } else if (MODE == 1) {
                #pragma unroll
                for (int hf = 0; hf < 2; hf++) {
                    const int rr = row + hf * 8;
                    const float v0 = acc[mt][nt][hf * 2 + 0] * hScale;
                    const float v1 = acc[mt][nt][hf * 2 + 1] * hScale;
                    const __half h0 = __float2half_rn(v0);
                    const __half h1 = __float2half_rn(v1);
                    const __half l0 = __float2half_rn(v0 - __half2float(h0));
                    const __half l1 = __float2half_rn(v1 - __half2float(h1));
                    const size_t o = (size_t)b * cBatch + (size_t)rr * cRow + col;
                    *(__half2*)(Ch + o) = __halves2half2(h0, h1);
                    *(__half2*)(Cl + o) = __halves2half2(l0, l1);
                }
            } else {  // MODE 2
                if (m0 < 512) {
                    float* c0 = Cf + (size_t)b * cBatch + (size_t)row * cRow + col;
                    float* c1 = Cf + (size_t)b * cBatch + (size_t)(row + 8) * cRow + col;
                    *(float2*)c0 = make_float2(acc[mt][nt][0] * invScale,
                                               acc[mt][nt][1] * invScale);
                    *(float2*)c1 = make_float2(acc[mt][nt][2] * invScale,
                                               acc[mt][nt][3] * invScale);
                } else {
                    #pragma unroll
                    for (int hf = 0; hf < 2; hf++) {
                        const int rr = row - 512 + hf * 8;
                        const float v0 = acc[mt][nt][hf * 2 + 0] * invScale;
                        const float v1 = acc[mt][nt][hf * 2 + 1] * invScale;
                        const size_t o = (size_t)b * cBatch + (size_t)rr * cRow + col;
                        *(__half2*)(Ch + o) =
                            __halves2half2(__float2half_rn(v0), __float2half_rn(v1));
                    }
                }
            }
        }
    }
}

// ---------------------------------------------------------------------------
// context_mma: part[sp][bh][d][e] = sum_{n in split sp} kh[d,n] * v[e,n]
// ---------------------------------------------------------------------------
#define CTX_ROWB 144
#define CTX_MAT  (64 * CTX_ROWB)
#define CTX_STAGE (2 * CTX_MAT)

__global__ __launch_bounds__(256)
void context_mma(const __half* __restrict__ kh, const __half* __restrict__ v,
                 float* __restrict__ part)
{
    __shared__ __align__(16) char smem[2 * CTX_STAGE];
    const uint32_t sb = smem_u32(smem);
    const int t = threadIdx.x;
    const int lane = t & 31;
    const int warp = t >> 5;
    const int wm = (warp & 1) * 32;
    const int wn = (warp >> 1) * 16;
    const int sp = blockIdx.x;
    const int bh = blockIdx.y;
    const int b = bh >> 3, h = bh & 7;

    const __half* ka = kh + (size_t)(b * HID + h * 64) * LDIM + sp * 1024;
    const __half* va = v  + (size_t)(b * HID + h * 64) * LDIM + sp * 1024;

    const uint32_t aOff = (uint32_t)((lane & 15) * CTX_ROWB + (lane >> 4) * 16);
    const uint32_t bOff = (uint32_t)(((lane & 7) + ((lane >> 4) << 3)) * CTX_ROWB
                                     + (((lane >> 3) & 1) * 16));

    float acc[2][2][4] = {};

    auto load_chunk = [&](int c, int buf) {
        const int k0 = c * 64;
        const uint32_t base = sb + (uint32_t)buf * CTX_STAGE;
        #pragma unroll
        for (int i = 0; i < 4; i++) {
            const int idx = t + i * 256;
            const int mat = idx >> 9;
            const int rr = (idx >> 3) & 63;
            const int s = idx & 7;
            const uint32_t dst = base + (uint32_t)(mat * CTX_MAT + rr * CTX_ROWB + s * 16);
            const __half* src = (mat == 0 ? ka : va) + (size_t)rr * LDIM + k0 + s * 8;
            cp_async16(dst, src);
        }
    };

    load_chunk(0, 0); cp_commit();

    for (int c = 0; c < 16; c++) {
        if (c < 15) { load_chunk(c + 1, (c + 1) & 1); cp_commit(); cp_wait1(); }
        else        { cp_wait0(); }
        __syncthreads();

        const uint32_t base = sb + (uint32_t)(c & 1) * CTX_STAGE;
        #pragma unroll
        for (int ks = 0; ks < 4; ks++) {
            const uint32_t kb = (uint32_t)(ks * 32);
            uint32_t a[2][4];
            #pragma unroll
            for (int mt = 0; mt < 2; mt++)
                ldsm_x4(a[mt], base + (uint32_t)((wm + mt * 16) * CTX_ROWB) + aOff + kb);
            uint32_t r4[4];
            ldsm_x4(r4, base + CTX_MAT + (uint32_t)(wn * CTX_ROWB) + bOff + kb);
            uint32_t bf[2][2] = {{r4[0], r4[1]}, {r4[2], r4[3]}};
            #pragma unroll
            for (int mt = 0; mt < 2; mt++)
                #pragma unroll
                for (int nt = 0; nt < 2; nt++)
                    mma_fp16(acc[mt][nt], a[mt], bf[nt]);
        }
        __syncthreads();
    }

    float* pp = part + (size_t)(sp * 64 + bh) * (DIMH * DIMH);
    #pragma unroll
    for (int mt = 0; mt < 2; mt++) {
        const int row = wm + mt * 16 + (lane >> 2);
        #pragma unroll
        for (int nt = 0; nt < 2; nt++) {
            const int col = wn + nt * 8 + 2 * (lane & 3);
            *(float2*)(pp + (size_t)row * 64 + col)
                = make_float2(acc[mt][nt][0], acc[mt][nt][1]);
            *(float2*)(pp + (size_t)(row + 8) * 64 + col)
                = make_float2(acc[mt][nt][2], acc[mt][nt][3]);
        }
    }
}

__global__ __launch_bounds__(256)
void ctx_reduce4(const float* __restrict__ part, float* __restrict__ ctx)
{
    const int i = blockIdx.x * 1024 + threadIdx.x * 4;
    float4 s = *(const float4*)(part + i);
    #pragma unroll
    for (int c = 1; c < 4; c++) {
        float4 p = *(const float4*)(part + (size_t)c * 64 * DIMH * DIMH + i);
        s.x += p.x; s.y += p.y; s.z += p.z; s.w += p.w;
    }
    *(float4*)(ctx + i) = s;
}

// ---------------------------------------------------------------------------
// Conversions
// ---------------------------------------------------------------------------
__global__ __launch_bounds__(256)
void conv_w1(const float* __restrict__ in, __half* __restrict__ hi, int n)
{
    int i = blockIdx.x * 256 + threadIdx.x;
    if (i >= n) return;
    hi[i] = __float2half_rn(in[i] * 64.0f);
}

__global__ __launch_bounds__(256)
void conv_wsplit(const float* __restrict__ in, __half* __restrict__ hi,
                 __half* __restrict__ lo, int n)
{
    int i = blockIdx.x * 256 + threadIdx.x;
    if (i >= n) return;
    float v = in[i] * 64.0f;
    __half h = __float2half_rn(v);
    hi[i] = h;
    lo[i] = __float2half_rn(v - __half2float(h));
}

__global__ __launch_bounds__(256)
void conv_xT(const float* __restrict__ x, __half* __restrict__ xh)
{
    __shared__ float tile[32][33];
    const int l0 = blockIdx.x * 32, c0 = blockIdx.y * 32, b = blockIdx.z;
    const float* xb = x + (size_t)b * CDIM * LDIM;
    const int tr = threadIdx.x >> 5;
    const int tc = threadIdx.x & 31;

    #pragma unroll
    for (int i = 0; i < 4; i++) {
        const int c = tr + i * 8;
        tile[c][tc] = xb[(size_t)(c0 + c) * LDIM + l0 + tc];
    }
    __syncthreads();

    __half* oh = xh + (size_t)b * LDIM * CDIM;
    #pragma unroll
    for (int i = 0; i < 4; i++) {
        const int l = tr + i * 8;
        oh[(size_t)(l0 + l) * CDIM + c0 + tc] = __float2half_rn(tile[tc][l]);
    }
}

// ---------------------------------------------------------------------------
// softmax over L, fp32 in -> fp16 out
// ---------------------------------------------------------------------------
__global__ __launch_bounds__(256)
void softmax_k(const float* __restrict__ kin, __half* __restrict__ kout)
{
    const size_t off = (size_t)blockIdx.y * (HID * LDIM) + (size_t)blockIdx.x * LDIM;
    const float* p = kin + off;
    __half* q = kout + off;
    const int t = threadIdx.x;

    float buf[16];
    float m = -1e30f;
    #pragma unroll
    for (int c = 0; c < 4; c++) {
        float4 v = *(const float4*)(p + c * 1024 + t * 4);
        buf[c * 4 + 0] = v.x; buf[c * 4 + 1] = v.y;
        buf[c * 4 + 2] = v.z; buf[c * 4 + 3] = v.w;
        m = fmaxf(m, fmaxf(fmaxf(v.x, v.y), fmaxf(v.z, v.w)));
    }

    __shared__ float redmax[8];
    __shared__ float redsum[8];

    #pragma unroll
    for (int o = 16; o; o >>= 1) m = fmaxf(m, __shfl_xor_sync(0xffffffffu, m, o));
    if ((t & 31) == 0) redmax[t >> 5] = m;
    __syncthreads();
    m = redmax[0];
    #pragma unroll
    for (int i = 1; i < 8; i++) m = fmaxf(m, redmax[i]);

    float s = 0.0f;
    #pragma unroll
    for (int i = 0; i < 16; i++) { buf[i] = expf(buf[i] - m); s += buf[i]; }

    #pragma unroll
    for (int o = 16; o; o >>= 1) s += __shfl_xor_sync(0xffffffffu, s, o);
    if ((t & 31) == 0) redsum[t >> 5] = s;
    __syncthreads();
    s = 0.0f;
    #pragma unroll
    for (int i = 0; i < 8; i++) s += redsum[i];
    const float inv = 1.0f / s;

    #pragma unroll
    for (int c = 0; c < 4; c++) {
        __half2 h0 = __halves2half2(__float2half_rn(buf[c * 4 + 0] * inv),
                                    __float2half_rn(buf[c * 4 + 1] * inv));
        __half2 h1 = __halves2half2(__float2half_rn(buf[c * 4 + 2] * inv),
                                    __float2half_rn(buf[c * 4 + 3] * inv));
        *(__half2*)(q + c * 1024 + t * 4)     = h0;
        *(__half2*)(q + c * 1024 + t * 4 + 2) = h1;
    }
}

// ---------------------------------------------------------------------------
// make_Ab: A_bT[c][(h,e)] = sum_d ctx[b,h,d,e] * W_q[(h,d),c] -> fp16
// ---------------------------------------------------------------------------
__global__ __launch_bounds__(256)
void make_Ab(const float* __restrict__ ctx, const float* __restrict__ w_qkv,
             __half* __restrict__ Abt)
{
    const int cc = blockIdx.x;
    const int bh = blockIdx.y;
    const int b = bh >> 3, h = bh & 7;

    __shared__ float Cs[64 * 64];
    __shared__ float Ws[64][65];

    const int t = threadIdx.x;
    const float* cp = ctx + (size_t)bh * (DIMH * DIMH);
    for (int i = t; i < 4096; i += 256) Cs[i] = cp[i];
    for (int i = t; i < 4096; i += 256) {
        const int d = i >> 6, c = i & 63;
        Ws[d][c] = w_qkv[(size_t)(h * 64 + d) * CDIM + cc * 64 + c];
    }
    __syncthreads();

    for (int i = t; i < 4096; i += 256) {
        const int c = i >> 6, e = i & 63;
        float s = 0.0f;
        #pragma unroll 8
        for (int d = 0; d < 64; d++) s = fmaf(Cs[d * 64 + e], Ws[d][c], s);
        Abt[(size_t)b * (CDIM * HID) + (size_t)(cc * 64 + c) * HID + h * 64 + e]
            = __float2half_rn(s);
    }
}

// ---------------------------------------------------------------------------
// Launch
// ---------------------------------------------------------------------------
extern "C" void kernel_launch(void* const* d_in, const int* in_sizes, int n_in,
                              void* d_out, int out_size)
{
    const float* x     = (const float*)d_in[0];
    const float* w_qkv = (const float*)d_in[1];
    const float* w_out = (const float*)d_in[2];
    const float* b_out = (const float*)d_in[3];
    float* out = (float*)d_out;

    float *k32, *part, *ctx;
    __half *kh, *v16, *xT, *wk, *woh, *wol, *Abt, *Mbh, *Mbl;
    cudaGetSymbolAddress((void**)&k32,  g_k);
    cudaGetSymbolAddress((void**)&kh,   g_kh);
    cudaGetSymbolAddress((void**)&v16,  g_v);
    cudaGetSymbolAddress((void**)&part, g_part);
    cudaGetSymbolAddress((void**)&ctx,  g_ctx);
    cudaGetSymbolAddress((void**)&xT,   g_xT);
    cudaGetSymbolAddress((void**)&wk,   g_wk);
    cudaGetSymbolAddress((void**)&woh,  g_wo_h);
    cudaGetSymbolAddress((void**)&wol,  g_wo_l);
    cudaGetSymbolAddress((void**)&Abt,  g_Abt);
    cudaGetSymbolAddress((void**)&Mbh,  g_Mb_h);
    cudaGetSymbolAddress((void**)&Mbl,  g_Mb_l);

    cudaFuncSetAttribute((const void*)tc2<2, 1>, cudaFuncAttributeMaxDynamicSharedMemorySize, TC_SMEM1);
    cudaFuncSetAttribute((const void*)tc2<1, 2>, cudaFuncAttributeMaxDynamicSharedMemorySize, TC_SMEM2);
    cudaFuncSetAttribute((const void*)tc2<0, 1>, cudaFuncAttributeMaxDynamicSharedMemorySize, TC_SMEM1);

    const dim3 blk(256);
    const long sX  = (long)CDIM * LDIM;
    const long sXT = (long)LDIM * CDIM;
    const long sK  = (long)HID * LDIM;

    // 0) conversions
    conv_w1<<<(2 * HID * CDIM + 255) / 256, blk>>>(
        w_qkv + (size_t)HID * CDIM, wk, 2 * HID * CDIM);
    conv_wsplit<<<(CDIM * HID + 255) / 256, blk>>>(w_out, woh, wol, CDIM * HID);
    conv_xT<<<dim3(LDIM / 32, CDIM / 32, BATCH), blk>>>(x, xT);

    // 1) GEMM1 (1-term): k (fp32) + v (fp16) = W_kv @ x_b
    tc2<2, 1><<<dim3(LDIM / 128, (2 * HID) / 128, BATCH), blk, TC_SMEM1>>>(
        wk, nullptr, 0L, xT, sXT, k32, v16, nullptr,
        sK, LDIM, nullptr, 1.0f / 64.0f, 0.0f);

    // 2) softmax: k fp32 -> k̂ fp16
    softmax_k<<<dim3(HID, BATCH), blk>>>(k32, kh);

    // 3) context (tensor core, split-K 4) + reduce
    context_mma<<<dim3(4, 64), blk>>>(kh, v16, part);
    ctx_reduce4<<<(64 * DIMH * DIMH) / 1024, blk>>>(part, ctx);

    // 4) A_b^T fp16
    make_Ab<<<dim3(8, 64), blk>>>(ctx, w_qkv, Abt);

    // 5) M_b = w_out @ A_b -> fp16 split of 2048*M_b (2-term)
    tc2<1, 2><<<dim3(CDIM / 128, CDIM / 128, BATCH), blk, TC_SMEM2>>>(
        woh, wol, 0L, Abt, (long)CDIM * HID, nullptr, Mbh, Mbl,
        (long)CDIM * CDIM, CDIM, nullptr, 0.0f, 32.0f);

    // 6) out = M_b @ x_b + b_out (1-term: reads only Mb_hi)
    tc2<0, 1><<<dim3(LDIM / 128, CDIM / 128, BATCH), blk, TC_SMEM1>>>(
        Mbh, nullptr, (long)CDIM * CDIM, xT, sXT, out, nullptr, nullptr,
        sX, LDIM, b_out, 1.0f / 2048.0f, 0.0f);
}

// round 11
// speedup vs baseline: 1.5824x; 1.0504x over previous
#include <cuda_runtime.h>
#include <cuda_fp16.h>
#include <math.h>
#include <stdint.h>

// Problem constants
#define BATCH 8
#define CDIM  512
#define LDIM  4096
#define HEADS 8
#define DIMH  64
#define HID   512   // HEADS*DIMH

// ---------------------------------------------------------------------------
// Scratch (static __device__ arrays)
// ---------------------------------------------------------------------------
__device__ __half g_kh [(size_t)BATCH * HID * LDIM];      // fp16 k logits -> softmaxed in place
__device__ __half g_v  [(size_t)BATCH * HID * LDIM];      // fp16 v
__device__ float  g_part[(size_t)4 * 64 * DIMH * DIMH];   // context split-K partials

__device__ __half g_xT  [(size_t)BATCH * LDIM * CDIM];    // fp16(x)^T [b][l][c]
__device__ __half g_wk  [(size_t)(2 * HID) * CDIM];       // fp16(64*W_kv)
__device__ __half g_wo  [(size_t)CDIM * HID];             // fp16(64*W_out)
__device__ __half g_Abt [(size_t)BATCH * CDIM * HID];     // fp16(A_b^T) [b][c][hid]
__device__ __half g_Mb  [(size_t)BATCH * CDIM * CDIM];    // fp16(2048*M_b)

// ---------------------------------------------------------------------------
// PTX helpers
// ---------------------------------------------------------------------------
__device__ __forceinline__ uint32_t smem_u32(const void* p) {
    uint32_t a;
    asm("{ .reg .u64 t; cvta.to.shared.u64 t, %1; cvt.u32.u64 %0, t; }" : "=r"(a) : "l"(p));
    return a;
}
__device__ __forceinline__ void cp_async16(uint32_t dst, const void* src) {
    asm volatile("cp.async.cg.shared.global [%0], [%1], 16;" :: "r"(dst), "l"(src));
}
__device__ __forceinline__ void cp_commit() { asm volatile("cp.async.commit_group;" ::: "memory"); }
__device__ __forceinline__ void cp_wait1()  { asm volatile("cp.async.wait_group 1;" ::: "memory"); }
__device__ __forceinline__ void cp_wait0()  { asm volatile("cp.async.wait_group 0;" ::: "memory"); }
__device__ __forceinline__ void ldsm_x4(uint32_t* r, uint32_t addr) {
    asm volatile("ldmatrix.sync.aligned.m8n8.x4.shared.b16 {%0,%1,%2,%3}, [%4];"
                 : "=r"(r[0]), "=r"(r[1]), "=r"(r[2]), "=r"(r[3]) : "r"(addr));
}
__device__ __forceinline__ void mma_fp16(float* c, const uint32_t* a, const uint32_t* b) {
    asm volatile(
        "mma.sync.aligned.m16n8k16.row.col.f32.f16.f16.f32 "
        "{%0,%1,%2,%3}, {%4,%5,%6,%7}, {%8,%9}, {%0,%1,%2,%3};"
        : "+f"(c[0]), "+f"(c[1]), "+f"(c[2]), "+f"(c[3])
        : "r"(a[0]), "r"(a[1]), "r"(a[2]), "r"(a[3]), "r"(b[0]), "r"(b[1]));
}

// ---------------------------------------------------------------------------
// tc2: C[b][m][n] = sum_k (Ah [+Al])[m,k] * Bh[n,k]  (TERMS-term fp16, K=512)
// CTA tile 128x128, K-chunk 64, 3-stage cp.async, 256 thr = 8 warps (4Mx2N),
// warp tile 32x64, <=128 regs -> 2 CTAs/SM.
// MODE 0: fp32 out = acc*invScale (+bias)
// MODE 2: GEMM1 — m0<512: fp16 (acc*invScale) -> Ch (k logits);
//                 m0>=512: fp16 (acc*invScale) -> Cl at row-512 (v).
// MODE 3: fp16 out = acc*hScale -> Ch only.
// ---------------------------------------------------------------------------
#define ROWB   144
#define A_MAT  (128 * ROWB)          // 18432
#define B_MAT  (128 * ROWB)          // 18432
#define TC_SMEM1 (3 * (A_MAT + B_MAT))      // 110592 (TERMS=1)
#define TC_SMEM2 (3 * (2 * A_MAT + B_MAT))  // 165888 (TERMS=2)

template<int MODE, int TERMS>
__global__ __launch_bounds__(256, 2)
void tc2(const __half* __restrict__ Ah, const __half* __restrict__ Al, long aBatch,
         const __half* __restrict__ Bh, long bBatch,
         float* __restrict__ Cf, __half* __restrict__ Ch, __half* __restrict__ Cl,
         long cBatch, int cRow,
         const float* __restrict__ bias, float invScale, float hScale)
{
    constexpr uint32_t STG  = (uint32_t)(TERMS * A_MAT + B_MAT);
    constexpr uint32_t BOFS = (uint32_t)(TERMS * A_MAT);

    extern __shared__ char smem[];
    const uint32_t sb = smem_u32(smem);
    const int t = threadIdx.x;
    const int lane = t & 31;
    const int warp = t >> 5;
    const int wm = (warp & 3) * 32;
    const int wn = (warp >> 2) * 64;
    const int n0 = blockIdx.x * 128;
    const int m0 = blockIdx.y * 128;
    const int b = blockIdx.z;

    Ah += (size_t)b * aBatch;
    if (TERMS == 2) Al += (size_t)b * aBatch;
    Bh += (size_t)b * bBatch;

    const uint32_t aOff = (uint32_t)((lane & 15) * ROWB + (lane >> 4) * 16);
    const uint32_t bOff = (uint32_t)(((lane & 7) + ((lane >> 4) << 3)) * ROWB
                                     + (((lane >> 3) & 1) * 16));

    float acc[2][8][4] = {};

    auto load_chunk = [&](int c, int buf) {
        const int k0 = c * 64;
        const uint32_t base = sb + (uint32_t)buf * STG;
        #pragma unroll
        for (int i = 0; i < 4; i++) {
            const int idx = t + i * 256;
            const int r = idx >> 3, s = idx & 7;
            const uint32_t dst = base + (uint32_t)(r * ROWB + s * 16);
            const size_t ga = (size_t)(m0 + r) * 512 + k0 + s * 8;
            cp_async16(dst, Ah + ga);
            if (TERMS == 2) cp_async16(dst + A_MAT, Al + ga);
        }
        #pragma unroll
        for (int i = 0; i < 4; i++) {
            const int idx = t + i * 256;
            const int r = idx >> 3, s = idx & 7;
            const uint32_t dst = base + BOFS + (uint32_t)(r * ROWB + s * 16);
            cp_async16(dst, Bh + (size_t)(n0 + r) * 512 + k0 + s * 8);
        }
    };

    load_chunk(0, 0); cp_commit();
    load_chunk(1, 1); cp_commit();

    for (int c = 0; c < 8; c++) {
        if (c < 7) cp_wait1(); else cp_wait0();
        __syncthreads();
        if (c < 6) { load_chunk(c + 2, (c + 2) % 3); cp_commit(); }

        const uint32_t base = sb + (uint32_t)(c % 3) * STG;
        #pragma unroll
        for (int ks = 0; ks < 4; ks++) {
            const uint32_t kb = (uint32_t)(ks * 32);
            uint32_t ah[2][4], al[2][4];
            #pragma unroll
            for (int mt = 0; mt < 2; mt++) {
                const uint32_t ra = base + (uint32_t)((wm + mt * 16) * ROWB) + aOff + kb;
                ldsm_x4(ah[mt], ra);
                if (TERMS == 2) ldsm_x4(al[mt], ra + A_MAT);
            }
            uint32_t bfr[8][2];
            #pragma unroll
            for (int np = 0; np < 4; np++) {
                uint32_t r4[4];
                const uint32_t rb = base + BOFS
                    + (uint32_t)((wn + np * 16) * ROWB) + bOff + kb;
                ldsm_x4(r4, rb);
                bfr[np * 2][0] = r4[0]; bfr[np * 2][1] = r4[1];
                bfr[np * 2 + 1][0] = r4[2]; bfr[np * 2 + 1][1] = r4[3];
            }
            #pragma unroll
            for (int mt = 0; mt < 2; mt++)
                #pragma unroll
                for (int nt = 0; nt < 8; nt++) {
                    mma_fp16(acc[mt][nt], ah[mt], bfr[nt]);
                    if (TERMS == 2) mma_fp16(acc[mt][nt], al[mt], bfr[nt]);
                }
        }
        __syncthreads();
    }

    // ---- epilogue ----
    #pragma unroll
    for (int mt = 0; mt < 2; mt++) {
        const int row = m0 + wm + mt * 16 + (lane >> 2);
        float bv0 = 0.0f, bv1 = 0.0f;
        if (MODE == 0 && bias) { bv0 = bias[row]; bv1 = bias[row + 8]; }
        #pragma unroll
        for (int nt = 0; nt < 8; nt++) {
            const int col = n0 + wn + nt * 8 + 2 * (lane & 3);
            if (MODE == 0) {
                float* c0 = Cf + (size_t)b * cBatch + (size_t)row * cRow + col;
                float* c1 = Cf + (size_t)b * cBatch + (size_t)(row + 8) * cRow + col;
                *(float2*)c0 = make_float2(acc[mt][nt][0] * invScale + bv0,
                                           acc[mt][nt][1] * invScale + bv0);
                *(float2*)c1 = make_float2(acc[mt][nt][2] * invScale + bv1,
                                           acc[mt][nt][3] * invScale + bv1);
            } else if (MODE == 2) {
                #pragma unroll
                for (int hf = 0; hf < 2; hf++) {
                    const int rr = row + hf * 8;
                    const float v0 = acc[mt][nt][hf * 2 + 0] * invScale;
                    const float v1 = acc[mt][nt][hf * 2 + 1] * invScale;
                    __half* dst = (m0 < 512)
                        ? (Ch + (size_t)b * cBatch + (size_t)rr * cRow + col)
                        : (Cl + (size_t)b * cBatch + (size_t)(rr - 512) * cRow + col);
                    *(__half2*)dst =
                        __halves2half2(__float2half_rn(v0), __float2half_rn(v1));
                }
            } else {  // MODE 3
                #pragma unroll
                for (int hf = 0; hf < 2; hf++) {
                    const int rr = row + hf * 8;
                    const float v0 = acc[mt][nt][hf * 2 + 0] * hScale;
                    const float v1 = acc[mt][nt][hf * 2 + 1] * hScale;
                    const size_t o = (size_t)b * cBatch + (size_t)rr * cRow + col;
                    *(__half2*)(Ch + o) =
                        __halves2half2(__float2half_rn(v0), __float2half_rn(v1));
                }
            }
        }
    }
}

// ---------------------------------------------------------------------------
// context_mma: part[sp][bh][d][e] = sum_{n in split sp} kh[d,n] * v[e,n]
// ---------------------------------------------------------------------------
#define CTX_ROWB 144
#define CTX_MAT  (64 * CTX_ROWB)
#define CTX_STAGE (2 * CTX_MAT)

__global__ __launch_bounds__(256)
void context_mma(const __half* __restrict__ kh, const __half* __restrict__ v,
                 float* __restrict__ part)
{
    __shared__ __align__(16) char smem[2 * CTX_STAGE];
    const uint32_t sb = smem_u32(smem);
    const int t = threadIdx.x;
    const int lane = t & 31;
    const int warp = t >> 5;
    const int wm = (warp & 1) * 32;
    const int wn = (warp >> 1) * 16;
    const int sp = blockIdx.x;
    const int bh = blockIdx.y;
    const int b = bh >> 3, h = bh & 7;

    const __half* ka = kh + (size_t)(b * HID + h * 64) * LDIM + sp * 1024;
    const __half* va = v  + (size_t)(b * HID + h * 64) * LDIM + sp * 1024;

    const uint32_t aOff = (uint32_t)((lane & 15) * CTX_ROWB + (lane >> 4) * 16);
    const uint32_t bOff = (uint32_t)(((lane & 7) + ((lane >> 4) << 3)) * CTX_ROWB
                                     + (((lane >> 3) & 1) * 16));

    float acc[2][2][4] = {};

    auto load_chunk = [&](int c, int buf) {
        const int k0 = c * 64;
        const uint32_t base = sb + (uint32_t)buf * CTX_STAGE;
        #pragma unroll
        for (int i = 0; i < 4; i++) {
            const int idx = t + i * 256;
            const int mat = idx >> 9;
            const int rr = (idx >> 3) & 63;
            const int s = idx & 7;
            const uint32_t dst = base + (uint32_t)(mat * CTX_MAT + rr * CTX_ROWB + s * 16);
            const __half* src = (mat == 0 ? ka : va) + (size_t)rr * LDIM + k0 + s * 8;
            cp_async16(dst, src);
        }
    };

    load_chunk(0, 0); cp_commit();

    for (int c = 0; c < 16; c++) {
        if (c < 15) { load_chunk(c + 1, (c + 1) & 1); cp_commit(); cp_wait1(); }
        else        { cp_wait0(); }
        __syncthreads();

        const uint32_t base = sb + (uint32_t)(c & 1) * CTX_STAGE;
        #pragma unroll
        for (int ks = 0; ks < 4; ks++) {
            const uint32_t kb = (uint32_t)(ks * 32);
            uint32_t a[2][4];
            #pragma unroll
            for (int mt = 0; mt < 2; mt++)
                ldsm_x4(a[mt], base + (uint32_t)((wm + mt * 16) * CTX_ROWB) + aOff + kb);
            uint32_t r4[4];
            ldsm_x4(r4, base + CTX_MAT + (uint32_t)(wn * CTX_ROWB) + bOff + kb);
            uint32_t bf[2][2] = {{r4[0], r4[1]}, {r4[2], r4[3]}};
            #pragma unroll
            for (int mt = 0; mt < 2; mt++)
                #pragma unroll
                for (int nt = 0; nt < 2; nt++)
                    mma_fp16(acc[mt][nt], a[mt], bf[nt]);
        }
        __syncthreads();
    }

    float* pp = part + (size_t)(sp * 64 + bh) * (DIMH * DIMH);
    #pragma unroll
    for (int mt = 0; mt < 2; mt++) {
        const int row = wm + mt * 16 + (lane >> 2);
        #pragma unroll
        for (int nt = 0; nt < 2; nt++) {
            const int col = wn + nt * 8 + 2 * (lane & 3);
            *(float2*)(pp + (size_t)row * 64 + col)
                = make_float2(acc[mt][nt][0], acc[mt][nt][1]);
            *(float2*)(pp + (size_t)(row + 8) * 64 + col)
                = make_float2(acc[mt][nt][2], acc[mt][nt][3]);
        }
    }
}

// ---------------------------------------------------------------------------
// Conversions
// ---------------------------------------------------------------------------
__global__ __launch_bounds__(256)
void conv_w1(const float* __restrict__ in, __half* __restrict__ hi, int n)
{
    int i = blockIdx.x * 256 + threadIdx.x;
    if (i >= n) return;
    hi[i] = __float2half_rn(in[i] * 64.0f);
}

// x[b][c][l] fp32 -> xT[b][l][c] fp16, 64x64 tiles, vectorized both sides
__global__ __launch_bounds__(256)
void conv_xT(const float* __restrict__ x, __half* __restrict__ xT)
{
    __shared__ __half tile[64][76];   // 152B rows: conflict-spread transpose
    const int l0 = blockIdx.x * 64, c0 = blockIdx.y * 64, b = blockIdx.z;
    const float* xb = x + (size_t)b * CDIM * LDIM;
    const int t = threadIdx.x;

    #pragma unroll
    for (int i = 0; i < 4; i++) {
        const int idx = t + i * 256;         // 0..1023
        const int c = idx >> 4;              // 0..63
        const int lq = (idx & 15) * 4;       // 0..60
        float4 v = *(const float4*)(xb + (size_t)(c0 + c) * LDIM + l0 + lq);
        tile[lq + 0][c] = __float2half_rn(v.x);
        tile[lq + 1][c] = __float2half_rn(v.y);
        tile[lq + 2][c] = __float2half_rn(v.z);
        tile[lq + 3][c] = __float2half_rn(v.w);
    }
    __syncthreads();

    __half* ob = xT + (size_t)b * LDIM * CDIM;
    #pragma unroll
    for (int i = 0; i < 8; i++) {
        const int idx = t + i * 256;         // 0..2047
        const int l = idx >> 5;              // 0..63
        const int cq = (idx & 31) * 2;       // 0..62
        *(__half2*)(ob + (size_t)(l0 + l) * CDIM + c0 + cq)
            = *(__half2*)(&tile[l][cq]);
    }
}

// ---------------------------------------------------------------------------
// softmax over L=4096, fp16 in-place. grid (512, BATCH), 256 threads.
// ---------------------------------------------------------------------------
__global__ __launch_bounds__(256)
void softmax_k(__half* __restrict__ kio)
{
    __half* p = kio + (size_t)blockIdx.y * (HID * LDIM) + (size_t)blockIdx.x * LDIM;
    const int t = threadIdx.x;

    float buf[16];
    float m = -1e30f;
    #pragma unroll
    for (int c = 0; c < 2; c++) {
        uint4 raw = *(const uint4*)(p + c * 2048 + t * 8);
        const __half2* h = (const __half2*)&raw;
        #pragma unroll
        for (int j = 0; j < 4; j++) {
            float2 f = __half22float2(h[j]);
            buf[c * 8 + j * 2 + 0] = f.x;
            buf[c * 8 + j * 2 + 1] = f.y;
            m = fmaxf(m, fmaxf(f.x, f.y));
        }
    }

    __shared__ float redmax[8];
    __shared__ float redsum[8];

    #pragma unroll
    for (int o = 16; o; o >>= 1) m = fmaxf(m, __shfl_xor_sync(0xffffffffu, m, o));
    if ((t & 31) == 0) redmax[t >> 5] = m;
    __syncthreads();
    m = redmax[0];
    #pragma unroll
    for (int i = 1; i < 8; i++) m = fmaxf(m, redmax[i]);

    float s = 0.0f;
    #pragma unroll
    for (int i = 0; i < 16; i++) { buf[i] = expf(buf[i] - m); s += buf[i]; }

    #pragma unroll
    for (int o = 16; o; o >>= 1) s += __shfl_xor_sync(0xffffffffu, s, o);
    if ((t & 31) == 0) redsum[t >> 5] = s;
    __syncthreads();
    s = 0.0f;
    #pragma unroll
    for (int i = 0; i < 8; i++) s += redsum[i];
    const float inv = 1.0f / s;

    #pragma unroll
    for (int c = 0; c < 2; c++) {
        uint4 raw;
        __half2* h = (__half2*)&raw;
        #pragma unroll
        for (int j = 0; j < 4; j++)
            h[j] = __floats2half2_rn(buf[c * 8 + j * 2] * inv,
                                     buf[c * 8 + j * 2 + 1] * inv);
        *(uint4*)(p + c * 2048 + t * 8) = raw;
    }
}

// ---------------------------------------------------------------------------
// make_Ab (fused split-K reduce):
// A_bT[c][(h,e)] = sum_d (sum_sp part[sp][bh][d][e]) * W_q[(h,d),c] -> fp16
// ---------------------------------------------------------------------------
__global__ __launch_bounds__(256)
void make_Ab(const float* __restrict__ part, const float* __restrict__ w_qkv,
             __half* __restrict__ Abt)
{
    const int cc = blockIdx.x;
    const int bh = blockIdx.y;
    const int b = bh >> 3, h = bh & 7;

    __shared__ float Cs[64 * 64];
    __shared__ float Ws[64][65];

    const int t = threadIdx.x;
    const float* pp = part + (size_t)bh * (DIMH * DIMH);
    for (int i = t; i < 4096; i += 256) {
        float s = pp[i];
        #pragma unroll
        for (int sp = 1; sp < 4; sp++)
            s += pp[(size_t)sp * 64 * DIMH * DIMH + i];
        Cs[i] = s;
    }
    for (int i = t; i < 4096; i += 256) {
        const int d = i >> 6, c = i & 63;
        Ws[d][c] = w_qkv[(size_t)(h * 64 + d) * CDIM + cc * 64 + c];
    }
    __syncthreads();

    for (int i = t; i < 4096; i += 256) {
        const int c = i >> 6, e = i & 63;
        float s = 0.0f;
        #pragma unroll 8
        for (int d = 0; d < 64; d++) s = fmaf(Cs[d * 64 + e], Ws[d][c], s);
        Abt[(size_t)b * (CDIM * HID) + (size_t)(cc * 64 + c) * HID + h * 64 + e]
            = __float2half_rn(s);
    }
}

// ---------------------------------------------------------------------------
// Launch
// ---------------------------------------------------------------------------
extern "C" void kernel_launch(void* const* d_in, const int* in_sizes, int n_in,
                              void* d_out, int out_size)
{
    const float* x     = (const float*)d_in[0];
    const float* w_qkv = (const float*)d_in[1];
    const float* w_out = (const float*)d_in[2];
    const float* b_out = (const float*)d_in[3];
    float* out = (float*)d_out;

    float *part;
    __half *kh, *v16, *xT, *wk, *wo, *Abt, *Mb;
    cudaGetSymbolAddress((void**)&kh,   g_kh);
    cudaGetSymbolAddress((void**)&v16,  g_v);
    cudaGetSymbolAddress((void**)&part, g_part);
    cudaGetSymbolAddress((void**)&xT,   g_xT);
    cudaGetSymbolAddress((void**)&wk,   g_wk);
    cudaGetSymbolAddress((void**)&wo,   g_wo);
    cudaGetSymbolAddress((void**)&Abt,  g_Abt);
    cudaGetSymbolAddress((void**)&Mb,   g_Mb);

    cudaFuncSetAttribute((const void*)tc2<2, 1>, cudaFuncAttributeMaxDynamicSharedMemorySize, TC_SMEM1);
    cudaFuncSetAttribute((const void*)tc2<3, 1>, cudaFuncAttributeMaxDynamicSharedMemorySize, TC_SMEM1);
    cudaFuncSetAttribute((const void*)tc2<0, 1>, cudaFuncAttributeMaxDynamicSharedMemorySize, TC_SMEM1);

    const dim3 blk(256);
    const long sX  = (long)CDIM * LDIM;
    const long sXT = (long)LDIM * CDIM;
    const long sK  = (long)HID * LDIM;

    // 0) conversions
    conv_w1<<<(2 * HID * CDIM + 255) / 256, blk>>>(
        w_qkv + (size_t)HID * CDIM, wk, 2 * HID * CDIM);
    conv_w1<<<(CDIM * HID + 255) / 256, blk>>>(w_out, wo, CDIM * HID);
    conv_xT<<<dim3(LDIM / 64, CDIM / 64, BATCH), blk>>>(x, xT);

    // 1) GEMM1 (1-term): k logits fp16 + v fp16 = W_kv @ x_b
    tc2<2, 1><<<dim3(LDIM / 128, (2 * HID) / 128, BATCH), blk, TC_SMEM1>>>(
        wk, nullptr, 0L, xT, sXT, nullptr, kh, v16,
        sK, LDIM, nullptr, 1.0f / 64.0f, 0.0f);

    // 2) softmax in place on fp16 k
    softmax_k<<<dim3(HID, BATCH), blk>>>(kh);

    // 3) context (tensor core, split-K 4); reduce fused into make_Ab
    context_mma<<<dim3(4, 64), blk>>>(kh, v16, part);

    // 4) A_b^T fp16 (with fused split-K reduction)
    make_Ab<<<dim3(8, 64), blk>>>(part, w_qkv, Abt);

    // 5) M_b = w_out @ A_b -> fp16(2048*M_b)  (1-term)
    tc2<3, 1><<<dim3(CDIM / 128, CDIM / 128, BATCH), blk, TC_SMEM1>>>(
        wo, nullptr, 0L, Abt, (long)CDIM * HID, nullptr, Mb, nullptr,
        (long)CDIM * CDIM, CDIM, nullptr, 0.0f, 32.0f);

    // 6) out = M_b @ x_b + b_out (1-term)
    tc2<0, 1><<<dim3(LDIM / 128, CDIM / 128, BATCH), blk, TC_SMEM1>>>(
        Mb, nullptr, (long)CDIM * CDIM, xT, sXT, out, nullptr, nullptr,
        sX, LDIM, b_out, 1.0f / 2048.0f, 0.0f);
}